// round 1
// baseline (speedup 1.0000x reference)
#include <cuda_runtime.h>
#include <cuda_bf16.h>

// ---------------------------------------------------------------------------
// Problem constants
// ---------------------------------------------------------------------------
#define BB 4
#define NN 2048
#define TOK (BB*NN)        // 8192
#define DD 256
#define HH 8
#define DH 32
#define LL 4
#define QK_SCALE 0.17677669529663687f   // 32^-0.5
#define LN_EPS 1e-5f

// ---------------------------------------------------------------------------
// Scratch (no allocation allowed -> __device__ globals)
// ---------------------------------------------------------------------------
__device__ float g_h  [TOK*DD];
__device__ float g_qkv[TOK*3*DD];
__device__ float g_q  [TOK*DD];
__device__ float g_k  [TOK*DD];
__device__ float g_v  [TOK*DD];
__device__ float g_o  [TOK*DD];
__device__ float g_t1 [TOK*2*DD];
__device__ float g_t2 [TOK*DD];
__device__ float g_rope[TOK*32];   // per token: [axis(2)][cos x8 | sin x8]

// ---------------------------------------------------------------------------
// Kernel 0: input projection (IN_DIM=1 outer product) + rope table
// ---------------------------------------------------------------------------
__global__ void proj_rope_init(const float* __restrict__ h_in,
                               const float* __restrict__ pos,
                               const float* __restrict__ pw,
                               const float* __restrict__ pb,
                               float* __restrict__ h,
                               float* __restrict__ rope)
{
    int t = blockIdx.x;
    int d = threadIdx.x;
    h[t*DD + d] = h_in[t]*pw[d] + pb[d];
    if (d < 16) {
        int axis = d >> 3, i = d & 7;
        // inv_freq = 10000^(-i/8)
        float freq = exp2f(-(float)i * (13.287712379549449f / 8.0f));
        float ang = pos[t*2 + axis] * 64.0f * freq;
        float s, c;
        sincosf(ang, &s, &c);
        rope[t*32 + axis*16 + i]     = c;
        rope[t*32 + axis*16 + 8 + i] = s;
    }
}

// ---------------------------------------------------------------------------
// Generic tiled SGEMM: C[M,N] = A[M,K] @ W[K,N] (+bias) (+relu)
// BM=BN=64, BK=16, 256 threads, 4x4 register tile.
// ---------------------------------------------------------------------------
__global__ void gemm_kernel(const float* __restrict__ A,
                            const float* __restrict__ W,
                            const float* __restrict__ bias,
                            float* __restrict__ C,
                            int M, int K, int N, int relu)
{
    __shared__ float As[16][64];   // transposed: As[k][m]
    __shared__ float Ws[16][64];   // Ws[k][n]

    int tid = threadIdx.x;
    int tx = tid & 15, ty = tid >> 4;
    int row0 = blockIdx.y * 64;
    int col0 = blockIdx.x * 64;

    int la_r = tid >> 2;            // 0..63
    int la_c = (tid & 3) * 4;       // k offset
    int lw_r = tid >> 4;            // 0..15
    int lw_c = (tid & 15) * 4;      // n offset

    float acc[4][4] = {};

    for (int kk = 0; kk < K; kk += 16) {
        float4 a4 = *(const float4*)&A[(long)(row0 + la_r)*K + kk + la_c];
        As[la_c+0][la_r] = a4.x;
        As[la_c+1][la_r] = a4.y;
        As[la_c+2][la_r] = a4.z;
        As[la_c+3][la_r] = a4.w;
        *(float4*)&Ws[lw_r][lw_c] = *(const float4*)&W[(long)(kk + lw_r)*N + col0 + lw_c];
        __syncthreads();
        #pragma unroll
        for (int k = 0; k < 16; k++) {
            float4 av = *(const float4*)&As[k][ty*4];
            float4 bv = *(const float4*)&Ws[k][tx*4];
            float a[4] = {av.x, av.y, av.z, av.w};
            float b[4] = {bv.x, bv.y, bv.z, bv.w};
            #pragma unroll
            for (int i = 0; i < 4; i++)
                #pragma unroll
                for (int j = 0; j < 4; j++)
                    acc[i][j] = fmaf(a[i], b[j], acc[i][j]);
        }
        __syncthreads();
    }

    #pragma unroll
    for (int i = 0; i < 4; i++) {
        long r = row0 + ty*4 + i;
        #pragma unroll
        for (int j = 0; j < 4; j++) {
            int c = col0 + tx*4 + j;
            float v = acc[i][j];
            if (bias) v += bias[c];
            if (relu) v = fmaxf(v, 0.0f);
            C[r*N + c] = v;
        }
    }
}

// ---------------------------------------------------------------------------
// Rope + split/transpose: qkv (TOK,768) -> Q/K/V in (bh, n, 32) layout.
// Q gets the 1/sqrt(DH) scale folded in.
// ---------------------------------------------------------------------------
__global__ void rope_kernel(const float* __restrict__ qkv,
                            const float* __restrict__ rope,
                            float* __restrict__ Q,
                            float* __restrict__ K,
                            float* __restrict__ V)
{
    int t = blockIdx.x;             // token 0..8191
    int tid = threadIdx.x;          // h*32 + d
    int hh = tid >> 5, d = tid & 31;
    int b = t >> 11, n = t & 2047;

    const float* base = qkv + (long)t*768;
    float qv = base[tid];
    float kv = base[256 + tid];
    float vv = base[512 + tid];

    int axis = d >> 4;              // 0: time axis, 1: x axis
    int dd = d & 15;
    int i = dd & 7;
    const float* rp = rope + t*32 + axis*16;
    float c = rp[i], s = rp[8 + i];

    float q2, k2;
    if (dd < 8) {
        float qy = base[tid + 8], ky = base[256 + tid + 8];
        q2 = qv*c - qy*s;
        k2 = kv*c - ky*s;
    } else {
        float qx = base[tid - 8], kx = base[256 + tid - 8];
        q2 = qx*s + qv*c;
        k2 = kx*s + kv*c;
    }

    long o = (((long)(b*HH + hh))*NN + n)*DH + d;
    Q[o] = q2 * QK_SCALE;
    K[o] = k2;
    V[o] = vv;
}

// ---------------------------------------------------------------------------
// Flash-style attention, fp32. One warp per query row; 32-key tiles in smem.
// grid: (N/8, B*H); block: 256 threads (8 warps = 8 queries).
// Output written directly in merged-head (token, 256) layout.
// ---------------------------------------------------------------------------
__global__ void attn_kernel(const float* __restrict__ Q,
                            const float* __restrict__ K,
                            const float* __restrict__ V,
                            float* __restrict__ O)
{
    __shared__ float ks[32*33];
    __shared__ float vs[32*33];

    int bh = blockIdx.y;
    int w = threadIdx.x >> 5, lane = threadIdx.x & 31;
    int qi = blockIdx.x*8 + w;

    const float* qp = Q + (((long)bh)*NN + qi)*DH;
    float qr[32];
    #pragma unroll
    for (int d = 0; d < 32; d++) qr[d] = qp[d];   // broadcast load

    const float* kb = K + ((long)bh)*NN*DH;
    const float* vb = V + ((long)bh)*NN*DH;

    float m = -1e30f, l = 0.0f, acc = 0.0f;

    for (int kt = 0; kt < NN; kt += 32) {
        __syncthreads();
        #pragma unroll
        for (int idx = threadIdx.x; idx < 1024; idx += 256) {
            int j = idx >> 5, d = idx & 31;
            ks[j*33 + d] = kb[(long)kt*32 + idx];
            vs[j*33 + d] = vb[(long)kt*32 + idx];
        }
        __syncthreads();

        // score for key (kt + lane)
        float s = 0.0f;
        #pragma unroll
        for (int d = 0; d < 32; d++)
            s = fmaf(qr[d], ks[lane*33 + d], s);

        // warp max
        float mt = s;
        #pragma unroll
        for (int o2 = 16; o2 > 0; o2 >>= 1)
            mt = fmaxf(mt, __shfl_xor_sync(0xffffffffu, mt, o2));
        float mn = fmaxf(m, mt);

        float corr = __expf(m - mn);
        acc *= corr;
        l   *= corr;

        float p = __expf(s - mn);
        #pragma unroll
        for (int j = 0; j < 32; j++) {
            float pj = __shfl_sync(0xffffffffu, p, j);
            acc = fmaf(pj, vs[j*33 + lane], acc);
            l  += pj;
        }
        m = mn;
    }

    int b = bh >> 3, hh = bh & 7;
    O[((long)b*NN + qi)*DD + hh*DH + lane] = acc / l;
}

// ---------------------------------------------------------------------------
// h = LayerNorm(h + r) * g + b      (block per token, 256 threads)
// ---------------------------------------------------------------------------
__global__ void add_ln_kernel(float* __restrict__ h,
                              const float* __restrict__ r,
                              const float* __restrict__ g,
                              const float* __restrict__ bta)
{
    int t = blockIdx.x, d = threadIdx.x;
    __shared__ float red[8];

    float x = h[(long)t*DD + d] + r[(long)t*DD + d];

    float s = x;
    #pragma unroll
    for (int o = 16; o > 0; o >>= 1) s += __shfl_xor_sync(0xffffffffu, s, o);
    if ((d & 31) == 0) red[d >> 5] = s;
    __syncthreads();
    float tot = 0.0f;
    #pragma unroll
    for (int i = 0; i < 8; i++) tot += red[i];
    float mean = tot * (1.0f/256.0f);
    float dx = x - mean;
    __syncthreads();

    float s2 = dx*dx;
    #pragma unroll
    for (int o = 16; o > 0; o >>= 1) s2 += __shfl_xor_sync(0xffffffffu, s2, o);
    if ((d & 31) == 0) red[d >> 5] = s2;
    __syncthreads();
    float ssq = 0.0f;
    #pragma unroll
    for (int i = 0; i < 8; i++) ssq += red[i];
    float var = ssq * (1.0f/256.0f);

    h[(long)t*DD + d] = dx * rsqrtf(var + LN_EPS) * g[d] + bta[d];
}

// ---------------------------------------------------------------------------
// Launcher
// ---------------------------------------------------------------------------
extern "C" void kernel_launch(void* const* d_in, const int* in_sizes, int n_in,
                              void* d_out, int out_size)
{
    const float* h_in    = (const float*)d_in[0];
    const float* pos     = (const float*)d_in[1];
    const float* proj_w  = (const float*)d_in[2];
    const float* proj_b  = (const float*)d_in[3];
    const float* qkv_w   = (const float*)d_in[4];
    const float* out_w   = (const float*)d_in[5];
    const float* out_b   = (const float*)d_in[6];
    const float* O_w     = (const float*)d_in[7];
    const float* O_b     = (const float*)d_in[8];
    const float* ffn1_w  = (const float*)d_in[9];
    const float* ffn1_b  = (const float*)d_in[10];
    const float* ffn2_w  = (const float*)d_in[11];
    const float* ffn2_b  = (const float*)d_in[12];
    const float* ln1_g   = (const float*)d_in[13];
    const float* ln1_b   = (const float*)d_in[14];
    const float* ln2_g   = (const float*)d_in[15];
    const float* ln2_b   = (const float*)d_in[16];
    const float* final_w = (const float*)d_in[17];

    float *h, *qkv, *q, *k, *v, *o, *t1, *t2, *rope;
    cudaGetSymbolAddress((void**)&h,    g_h);
    cudaGetSymbolAddress((void**)&qkv,  g_qkv);
    cudaGetSymbolAddress((void**)&q,    g_q);
    cudaGetSymbolAddress((void**)&k,    g_k);
    cudaGetSymbolAddress((void**)&v,    g_v);
    cudaGetSymbolAddress((void**)&o,    g_o);
    cudaGetSymbolAddress((void**)&t1,   g_t1);
    cudaGetSymbolAddress((void**)&t2,   g_t2);
    cudaGetSymbolAddress((void**)&rope, g_rope);

    proj_rope_init<<<TOK, 256>>>(h_in, pos, proj_w, proj_b, h, rope);

    for (int l = 0; l < LL; l++) {
        // qkv = h @ qkv_w[l]                     (8192,256) @ (256,768)
        gemm_kernel<<<dim3(12, 128), 256>>>(h, qkv_w + (long)l*DD*3*DD, nullptr,
                                            qkv, TOK, DD, 3*DD, 0);
        // rope + head split/transpose
        rope_kernel<<<TOK, 256>>>(qkv, rope, q, k, v);
        // attention -> merged-head output
        attn_kernel<<<dim3(NN/8, BB*HH), 256>>>(q, k, v, o);
        // o @ out_w + out_b
        gemm_kernel<<<dim3(4, 128), 256>>>(o, out_w + (long)l*DD*DD, out_b + l*DD,
                                           t2, TOK, DD, DD, 0);
        // @ O_w + O_b
        gemm_kernel<<<dim3(4, 128), 256>>>(t2, O_w + (long)l*DD*DD, O_b + l*DD,
                                           o, TOK, DD, DD, 0);
        // h = LN(h + o)
        add_ln_kernel<<<TOK, 256>>>(h, o, ln1_g + l*DD, ln1_b + l*DD);
        // ffn
        gemm_kernel<<<dim3(8, 128), 256>>>(h, ffn1_w + (long)l*DD*2*DD, ffn1_b + l*2*DD,
                                           t1, TOK, DD, 2*DD, 1);
        gemm_kernel<<<dim3(4, 128), 256>>>(t1, ffn2_w + (long)l*2*DD*DD, ffn2_b + l*DD,
                                           o, TOK, 2*DD, DD, 0);
        // h = LN(h + f)
        add_ln_kernel<<<TOK, 256>>>(h, o, ln2_g + l*DD, ln2_b + l*DD);
    }

    // out = h @ final_w
    gemm_kernel<<<dim3(4, 128), 256>>>(h, final_w, nullptr,
                                       (float*)d_out, TOK, DD, DD, 0);
}

// round 2
// speedup vs baseline: 2.4536x; 2.4536x over previous
#include <cuda_runtime.h>
#include <cuda_bf16.h>

// ---------------------------------------------------------------------------
// Problem constants
// ---------------------------------------------------------------------------
#define BB 4
#define NN 2048
#define TOK (BB*NN)        // 8192
#define DD 256
#define HH 8
#define DH 32
#define LL 4
#define QK_SCALE 0.17677669529663687f   // 32^-0.5
#define LN_EPS 1e-5f

// ---------------------------------------------------------------------------
// Scratch (no allocation allowed -> __device__ globals)
// ---------------------------------------------------------------------------
__device__ float g_h  [TOK*DD];
__device__ float g_qkv[TOK*3*DD];
__device__ float g_q  [TOK*DD];   // (bh, d, n)  transposed
__device__ float g_k  [TOK*DD];   // (bh, d, n)  transposed
__device__ float g_v  [TOK*DD];   // (bh, n, d)  natural
__device__ float g_o  [TOK*DD];
__device__ float g_t1 [TOK*2*DD];
__device__ float g_t2 [TOK*DD];
__device__ float g_rope[TOK*32];   // per token: [axis(2)][cos x8 | sin x8]

// ---------------------------------------------------------------------------
// Kernel 0: input projection (IN_DIM=1 outer product) + rope table
// ---------------------------------------------------------------------------
__global__ void proj_rope_init(const float* __restrict__ h_in,
                               const float* __restrict__ pos,
                               const float* __restrict__ pw,
                               const float* __restrict__ pb,
                               float* __restrict__ h,
                               float* __restrict__ rope)
{
    int t = blockIdx.x;
    int d = threadIdx.x;
    h[t*DD + d] = h_in[t]*pw[d] + pb[d];
    if (d < 16) {
        int axis = d >> 3, i = d & 7;
        float freq = exp2f(-(float)i * (13.287712379549449f / 8.0f));
        float ang = pos[t*2 + axis] * 64.0f * freq;
        float s, c;
        sincosf(ang, &s, &c);
        rope[t*32 + axis*16 + i]     = c;
        rope[t*32 + axis*16 + 8 + i] = s;
    }
}

// ---------------------------------------------------------------------------
// Generic tiled SGEMM: C[M,N] = A[M,K] @ W[K,N] (+bias) (+relu)
// ---------------------------------------------------------------------------
__global__ void gemm_kernel(const float* __restrict__ A,
                            const float* __restrict__ W,
                            const float* __restrict__ bias,
                            float* __restrict__ C,
                            int M, int K, int N, int relu)
{
    __shared__ float As[16][64];
    __shared__ float Ws[16][64];

    int tid = threadIdx.x;
    int tx = tid & 15, ty = tid >> 4;
    int row0 = blockIdx.y * 64;
    int col0 = blockIdx.x * 64;

    int la_r = tid >> 2;
    int la_c = (tid & 3) * 4;
    int lw_r = tid >> 4;
    int lw_c = (tid & 15) * 4;

    float acc[4][4] = {};

    for (int kk = 0; kk < K; kk += 16) {
        float4 a4 = *(const float4*)&A[(long)(row0 + la_r)*K + kk + la_c];
        As[la_c+0][la_r] = a4.x;
        As[la_c+1][la_r] = a4.y;
        As[la_c+2][la_r] = a4.z;
        As[la_c+3][la_r] = a4.w;
        *(float4*)&Ws[lw_r][lw_c] = *(const float4*)&W[(long)(kk + lw_r)*N + col0 + lw_c];
        __syncthreads();
        #pragma unroll
        for (int k = 0; k < 16; k++) {
            float4 av = *(const float4*)&As[k][ty*4];
            float4 bv = *(const float4*)&Ws[k][tx*4];
            float a[4] = {av.x, av.y, av.z, av.w};
            float b[4] = {bv.x, bv.y, bv.z, bv.w};
            #pragma unroll
            for (int i = 0; i < 4; i++)
                #pragma unroll
                for (int j = 0; j < 4; j++)
                    acc[i][j] = fmaf(a[i], b[j], acc[i][j]);
        }
        __syncthreads();
    }

    #pragma unroll
    for (int i = 0; i < 4; i++) {
        long r = row0 + ty*4 + i;
        #pragma unroll
        for (int j = 0; j < 4; j++) {
            int c = col0 + tx*4 + j;
            float v = acc[i][j];
            if (bias) v += bias[c];
            if (relu) v = fmaxf(v, 0.0f);
            C[r*N + c] = v;
        }
    }
}

// ---------------------------------------------------------------------------
// Rope + split: qkv (TOK,768) -> Q,K transposed (bh,d,n); V natural (bh,n,d).
// Q gets the 1/sqrt(DH) scale folded in.
// ---------------------------------------------------------------------------
__global__ void rope_kernel(const float* __restrict__ qkv,
                            const float* __restrict__ rope,
                            float* __restrict__ Q,
                            float* __restrict__ K,
                            float* __restrict__ V)
{
    int t = blockIdx.x;             // token 0..8191
    int tid = threadIdx.x;          // h*32 + d
    int hh = tid >> 5, d = tid & 31;
    int b = t >> 11, n = t & 2047;

    const float* base = qkv + (long)t*768;
    float qv = base[tid];
    float kv = base[256 + tid];
    float vv = base[512 + tid];

    int axis = d >> 4;
    int dd = d & 15;
    int i = dd & 7;
    const float* rp = rope + t*32 + axis*16;
    float c = rp[i], s = rp[8 + i];

    float q2, k2;
    if (dd < 8) {
        float qy = base[tid + 8], ky = base[256 + tid + 8];
        q2 = qv*c - qy*s;
        k2 = kv*c - ky*s;
    } else {
        float qx = base[tid - 8], kx = base[256 + tid - 8];
        q2 = qx*s + qv*c;
        k2 = kx*s + kv*c;
    }

    int bh = b*HH + hh;
    long oT = (((long)bh)*DH + d)*NN + n;       // transposed
    Q[oT] = q2 * QK_SCALE;
    K[oT] = k2;
    V[(((long)bh)*NN + n)*DH + d] = vv;         // natural
}

// ---------------------------------------------------------------------------
// Flash attention v2 (fp32), register-tiled.
// Block: 64 queries, 256 threads (16x16). Key tiles of 64.
// Qt/Kt in (bh, d, n) layout; V in (bh, n, d).
// Output in merged-head (token, 256) layout.
// ---------------------------------------------------------------------------
__global__ __launch_bounds__(256) void attn_kernel(
    const float* __restrict__ Qt,
    const float* __restrict__ Kt,
    const float* __restrict__ V,
    float* __restrict__ O)
{
    __shared__ float Qs[32][64];     // [d][q]
    __shared__ float Ks[32][64];     // [d][k]
    __shared__ float Vs[64][32];     // [k][d]
    __shared__ float Ps[64][68];     // [q][k] padded

    int bh = blockIdx.y;
    int qb = blockIdx.x;             // query block (64 queries)
    int tid = threadIdx.x;
    int tx = tid & 15, ty = tid >> 4;

    const float* qtp = Qt + (long)bh*DH*NN;
    const float* ktp = Kt + (long)bh*DH*NN;
    const float* vbp = V  + (long)bh*NN*DH;

    // load Q tile (32 d x 64 q)
    #pragma unroll
    for (int it = 0; it < 2; it++) {
        int fid = tid + it*256;          // 0..511
        int d = fid >> 4, c4 = (fid & 15)*4;
        *(float4*)&Qs[d][c4] = *(const float4*)&qtp[(long)d*NN + qb*64 + c4];
    }

    float m[4], l[4], acc[4][2];
    #pragma unroll
    for (int i = 0; i < 4; i++) { m[i] = -1e30f; l[i] = 0.f; acc[i][0] = 0.f; acc[i][1] = 0.f; }

    for (int kt0 = 0; kt0 < NN; kt0 += 64) {
        __syncthreads();   // protect Ks/Vs (and Q on first iter) vs previous reads
        #pragma unroll
        for (int it = 0; it < 2; it++) {
            int fid = tid + it*256;
            int d = fid >> 4, c4 = (fid & 15)*4;
            *(float4*)&Ks[d][c4] = *(const float4*)&ktp[(long)d*NN + kt0 + c4];
        }
        #pragma unroll
        for (int it = 0; it < 2; it++) {
            int fid = tid + it*256;
            int k = fid >> 3, d4 = (fid & 7)*4;
            *(float4*)&Vs[k][d4] = *(const float4*)&vbp[(long)(kt0 + k)*DH + d4];
        }
        __syncthreads();

        // S tile: 4x4 per thread, rows ty*4.., cols tx*4..
        float s[4][4] = {};
        #pragma unroll
        for (int d = 0; d < 32; d++) {
            float4 a = *(const float4*)&Qs[d][ty*4];
            float4 b = *(const float4*)&Ks[d][tx*4];
            s[0][0] = fmaf(a.x, b.x, s[0][0]); s[0][1] = fmaf(a.x, b.y, s[0][1]);
            s[0][2] = fmaf(a.x, b.z, s[0][2]); s[0][3] = fmaf(a.x, b.w, s[0][3]);
            s[1][0] = fmaf(a.y, b.x, s[1][0]); s[1][1] = fmaf(a.y, b.y, s[1][1]);
            s[1][2] = fmaf(a.y, b.z, s[1][2]); s[1][3] = fmaf(a.y, b.w, s[1][3]);
            s[2][0] = fmaf(a.z, b.x, s[2][0]); s[2][1] = fmaf(a.z, b.y, s[2][1]);
            s[2][2] = fmaf(a.z, b.z, s[2][2]); s[2][3] = fmaf(a.z, b.w, s[2][3]);
            s[3][0] = fmaf(a.w, b.x, s[3][0]); s[3][1] = fmaf(a.w, b.y, s[3][1]);
            s[3][2] = fmaf(a.w, b.z, s[3][2]); s[3][3] = fmaf(a.w, b.w, s[3][3]);
        }

        // online softmax per row strip; row spans the 16 tx-lanes
        #pragma unroll
        for (int i = 0; i < 4; i++) {
            float mt = fmaxf(fmaxf(s[i][0], s[i][1]), fmaxf(s[i][2], s[i][3]));
            #pragma unroll
            for (int o2 = 8; o2 > 0; o2 >>= 1)
                mt = fmaxf(mt, __shfl_xor_sync(0xffffffffu, mt, o2));
            float mn = fmaxf(m[i], mt);
            float corr = __expf(m[i] - mn);
            m[i] = mn;
            l[i]      *= corr;
            acc[i][0] *= corr;
            acc[i][1] *= corr;
            float p0 = __expf(s[i][0] - mn);
            float p1 = __expf(s[i][1] - mn);
            float p2 = __expf(s[i][2] - mn);
            float p3 = __expf(s[i][3] - mn);
            float ls = p0 + p1 + p2 + p3;
            #pragma unroll
            for (int o2 = 8; o2 > 0; o2 >>= 1)
                ls += __shfl_xor_sync(0xffffffffu, ls, o2);
            l[i] += ls;
            *(float4*)&Ps[ty*4 + i][tx*4] = make_float4(p0, p1, p2, p3);
        }
        __syncthreads();

        // O += P(64x64) @ V(64x32): rows ty*4.., cols tx*2..
        #pragma unroll
        for (int k4 = 0; k4 < 16; k4++) {
            float4 p0 = *(const float4*)&Ps[ty*4 + 0][k4*4];
            float4 p1 = *(const float4*)&Ps[ty*4 + 1][k4*4];
            float4 p2 = *(const float4*)&Ps[ty*4 + 2][k4*4];
            float4 p3 = *(const float4*)&Ps[ty*4 + 3][k4*4];
            float2 v0 = *(const float2*)&Vs[k4*4 + 0][tx*2];
            float2 v1 = *(const float2*)&Vs[k4*4 + 1][tx*2];
            float2 v2 = *(const float2*)&Vs[k4*4 + 2][tx*2];
            float2 v3 = *(const float2*)&Vs[k4*4 + 3][tx*2];
            acc[0][0] = fmaf(p0.x, v0.x, acc[0][0]); acc[0][1] = fmaf(p0.x, v0.y, acc[0][1]);
            acc[0][0] = fmaf(p0.y, v1.x, acc[0][0]); acc[0][1] = fmaf(p0.y, v1.y, acc[0][1]);
            acc[0][0] = fmaf(p0.z, v2.x, acc[0][0]); acc[0][1] = fmaf(p0.z, v2.y, acc[0][1]);
            acc[0][0] = fmaf(p0.w, v3.x, acc[0][0]); acc[0][1] = fmaf(p0.w, v3.y, acc[0][1]);
            acc[1][0] = fmaf(p1.x, v0.x, acc[1][0]); acc[1][1] = fmaf(p1.x, v0.y, acc[1][1]);
            acc[1][0] = fmaf(p1.y, v1.x, acc[1][0]); acc[1][1] = fmaf(p1.y, v1.y, acc[1][1]);
            acc[1][0] = fmaf(p1.z, v2.x, acc[1][0]); acc[1][1] = fmaf(p1.z, v2.y, acc[1][1]);
            acc[1][0] = fmaf(p1.w, v3.x, acc[1][0]); acc[1][1] = fmaf(p1.w, v3.y, acc[1][1]);
            acc[2][0] = fmaf(p2.x, v0.x, acc[2][0]); acc[2][1] = fmaf(p2.x, v0.y, acc[2][1]);
            acc[2][0] = fmaf(p2.y, v1.x, acc[2][0]); acc[2][1] = fmaf(p2.y, v1.y, acc[2][1]);
            acc[2][0] = fmaf(p2.z, v2.x, acc[2][0]); acc[2][1] = fmaf(p2.z, v2.y, acc[2][1]);
            acc[2][0] = fmaf(p2.w, v3.x, acc[2][0]); acc[2][1] = fmaf(p2.w, v3.y, acc[2][1]);
            acc[3][0] = fmaf(p3.x, v0.x, acc[3][0]); acc[3][1] = fmaf(p3.x, v0.y, acc[3][1]);
            acc[3][0] = fmaf(p3.y, v1.x, acc[3][0]); acc[3][1] = fmaf(p3.y, v1.y, acc[3][1]);
            acc[3][0] = fmaf(p3.z, v2.x, acc[3][0]); acc[3][1] = fmaf(p3.z, v2.y, acc[3][1]);
            acc[3][0] = fmaf(p3.w, v3.x, acc[3][0]); acc[3][1] = fmaf(p3.w, v3.y, acc[3][1]);
        }
    }

    // epilogue: normalize + store merged-head layout
    int b = bh >> 3, hh = bh & 7;
    #pragma unroll
    for (int i = 0; i < 4; i++) {
        long q = qb*64 + ty*4 + i;
        float inv = 1.0f / l[i];
        long o = ((long)b*NN + q)*DD + hh*DH + tx*2;
        O[o + 0] = acc[i][0] * inv;
        O[o + 1] = acc[i][1] * inv;
    }
}

// ---------------------------------------------------------------------------
// h = LayerNorm(h + r) * g + b      (block per token, 256 threads)
// ---------------------------------------------------------------------------
__global__ void add_ln_kernel(float* __restrict__ h,
                              const float* __restrict__ r,
                              const float* __restrict__ g,
                              const float* __restrict__ bta)
{
    int t = blockIdx.x, d = threadIdx.x;
    __shared__ float red[8];

    float x = h[(long)t*DD + d] + r[(long)t*DD + d];

    float s = x;
    #pragma unroll
    for (int o = 16; o > 0; o >>= 1) s += __shfl_xor_sync(0xffffffffu, s, o);
    if ((d & 31) == 0) red[d >> 5] = s;
    __syncthreads();
    float tot = 0.0f;
    #pragma unroll
    for (int i = 0; i < 8; i++) tot += red[i];
    float mean = tot * (1.0f/256.0f);
    float dx = x - mean;
    __syncthreads();

    float s2 = dx*dx;
    #pragma unroll
    for (int o = 16; o > 0; o >>= 1) s2 += __shfl_xor_sync(0xffffffffu, s2, o);
    if ((d & 31) == 0) red[d >> 5] = s2;
    __syncthreads();
    float ssq = 0.0f;
    #pragma unroll
    for (int i = 0; i < 8; i++) ssq += red[i];
    float var = ssq * (1.0f/256.0f);

    h[(long)t*DD + d] = dx * rsqrtf(var + LN_EPS) * g[d] + bta[d];
}

// ---------------------------------------------------------------------------
// Launcher
// ---------------------------------------------------------------------------
extern "C" void kernel_launch(void* const* d_in, const int* in_sizes, int n_in,
                              void* d_out, int out_size)
{
    const float* h_in    = (const float*)d_in[0];
    const float* pos     = (const float*)d_in[1];
    const float* proj_w  = (const float*)d_in[2];
    const float* proj_b  = (const float*)d_in[3];
    const float* qkv_w   = (const float*)d_in[4];
    const float* out_w   = (const float*)d_in[5];
    const float* out_b   = (const float*)d_in[6];
    const float* O_w     = (const float*)d_in[7];
    const float* O_b     = (const float*)d_in[8];
    const float* ffn1_w  = (const float*)d_in[9];
    const float* ffn1_b  = (const float*)d_in[10];
    const float* ffn2_w  = (const float*)d_in[11];
    const float* ffn2_b  = (const float*)d_in[12];
    const float* ln1_g   = (const float*)d_in[13];
    const float* ln1_b   = (const float*)d_in[14];
    const float* ln2_g   = (const float*)d_in[15];
    const float* ln2_b   = (const float*)d_in[16];
    const float* final_w = (const float*)d_in[17];

    float *h, *qkv, *q, *k, *v, *o, *t1, *t2, *rope;
    cudaGetSymbolAddress((void**)&h,    g_h);
    cudaGetSymbolAddress((void**)&qkv,  g_qkv);
    cudaGetSymbolAddress((void**)&q,    g_q);
    cudaGetSymbolAddress((void**)&k,    g_k);
    cudaGetSymbolAddress((void**)&v,    g_v);
    cudaGetSymbolAddress((void**)&o,    g_o);
    cudaGetSymbolAddress((void**)&t1,   g_t1);
    cudaGetSymbolAddress((void**)&t2,   g_t2);
    cudaGetSymbolAddress((void**)&rope, g_rope);

    proj_rope_init<<<TOK, 256>>>(h_in, pos, proj_w, proj_b, h, rope);

    for (int l = 0; l < LL; l++) {
        gemm_kernel<<<dim3(12, 128), 256>>>(h, qkv_w + (long)l*DD*3*DD, nullptr,
                                            qkv, TOK, DD, 3*DD, 0);
        rope_kernel<<<TOK, 256>>>(qkv, rope, q, k, v);
        attn_kernel<<<dim3(NN/64, BB*HH), 256>>>(q, k, v, o);
        gemm_kernel<<<dim3(4, 128), 256>>>(o, out_w + (long)l*DD*DD, out_b + l*DD,
                                           t2, TOK, DD, DD, 0);
        gemm_kernel<<<dim3(4, 128), 256>>>(t2, O_w + (long)l*DD*DD, O_b + l*DD,
                                           o, TOK, DD, DD, 0);
        add_ln_kernel<<<TOK, 256>>>(h, o, ln1_g + l*DD, ln1_b + l*DD);
        gemm_kernel<<<dim3(8, 128), 256>>>(h, ffn1_w + (long)l*DD*2*DD, ffn1_b + l*2*DD,
                                           t1, TOK, DD, 2*DD, 1);
        gemm_kernel<<<dim3(4, 128), 256>>>(t1, ffn2_w + (long)l*2*DD*DD, ffn2_b + l*DD,
                                           o, TOK, 2*DD, DD, 0);
        add_ln_kernel<<<TOK, 256>>>(h, o, ln2_g + l*DD, ln2_b + l*DD);
    }

    gemm_kernel<<<dim3(4, 128), 256>>>(h, final_w, nullptr,
                                       (float*)d_out, TOK, DD, DD, 0);
}

// round 5
// speedup vs baseline: 4.7954x; 1.9544x over previous
#include <cuda_runtime.h>
#include <cuda_bf16.h>
#include <cstdint>

// ---------------------------------------------------------------------------
// Problem constants
// ---------------------------------------------------------------------------
#define BB 4
#define NN 2048
#define TOK (BB*NN)        // 8192
#define DD 256
#define HH 8
#define DH 32
#define LL 4
#define QK_SCALE 0.17677669529663687f   // 32^-0.5
#define LN_EPS 1e-5f

// ---------------------------------------------------------------------------
// Scratch (no allocation allowed -> __device__ globals)
// ---------------------------------------------------------------------------
__device__ float g_h  [TOK*DD];
__device__ float g_qkv[TOK*3*DD];
__device__ __align__(16) __nv_bfloat16 g_q[TOK*DD];   // (bh, n, d) bf16
__device__ __align__(16) __nv_bfloat16 g_k[TOK*DD];   // (bh, n, d) bf16
__device__ __align__(16) __nv_bfloat16 g_v[TOK*DD];   // (bh, n, d) bf16
__device__ float g_o  [TOK*DD];
__device__ float g_t1 [TOK*2*DD];
__device__ float g_t2 [TOK*DD];
__device__ float g_rope[TOK*32];   // per token: [axis(2)][cos x8 | sin x8]

// ---------------------------------------------------------------------------
// PTX helpers (ldmatrix / bf16 mma)
// ---------------------------------------------------------------------------
__device__ __forceinline__ unsigned smem_u32(const void* p)
{
    return (unsigned)__cvta_generic_to_shared(p);
}

__device__ __forceinline__ void ldsm_x4(unsigned& r0, unsigned& r1,
                                        unsigned& r2, unsigned& r3, unsigned a)
{
    asm volatile("ldmatrix.sync.aligned.m8n8.x4.shared.b16 {%0,%1,%2,%3}, [%4];"
        : "=r"(r0), "=r"(r1), "=r"(r2), "=r"(r3) : "r"(a));
}

__device__ __forceinline__ void ldsm_x2(unsigned& r0, unsigned& r1, unsigned a)
{
    asm volatile("ldmatrix.sync.aligned.m8n8.x2.shared.b16 {%0,%1}, [%2];"
        : "=r"(r0), "=r"(r1) : "r"(a));
}

__device__ __forceinline__ void ldsm_x2_t(unsigned& r0, unsigned& r1, unsigned a)
{
    asm volatile("ldmatrix.sync.aligned.m8n8.x2.trans.shared.b16 {%0,%1}, [%2];"
        : "=r"(r0), "=r"(r1) : "r"(a));
}

__device__ __forceinline__ void mma_bf16(float& c0, float& c1, float& c2, float& c3,
                                         unsigned a0, unsigned a1, unsigned a2, unsigned a3,
                                         unsigned b0, unsigned b1)
{
    asm volatile("mma.sync.aligned.m16n8k16.row.col.f32.bf16.bf16.f32 "
        "{%0,%1,%2,%3}, {%4,%5,%6,%7}, {%8,%9}, {%0,%1,%2,%3};"
        : "+f"(c0), "+f"(c1), "+f"(c2), "+f"(c3)
        : "r"(a0), "r"(a1), "r"(a2), "r"(a3), "r"(b0), "r"(b1));
}

__device__ __forceinline__ unsigned pack_bf16x2(float lo, float hi)
{
    __nv_bfloat162 t = __floats2bfloat162_rn(lo, hi);
    unsigned u;
    memcpy(&u, &t, 4);
    return u;
}

// ---------------------------------------------------------------------------
// Kernel 0: input projection (IN_DIM=1 outer product) + rope table
// ---------------------------------------------------------------------------
__global__ void proj_rope_init(const float* __restrict__ h_in,
                               const float* __restrict__ pos,
                               const float* __restrict__ pw,
                               const float* __restrict__ pb,
                               float* __restrict__ h,
                               float* __restrict__ rope)
{
    int t = blockIdx.x;
    int d = threadIdx.x;
    h[t*DD + d] = h_in[t]*pw[d] + pb[d];
    if (d < 16) {
        int axis = d >> 3, i = d & 7;
        float freq = exp2f(-(float)i * (13.287712379549449f / 8.0f));
        float ang = pos[t*2 + axis] * 64.0f * freq;
        float s, c;
        sincosf(ang, &s, &c);
        rope[t*32 + axis*16 + i]     = c;
        rope[t*32 + axis*16 + 8 + i] = s;
    }
}

// ---------------------------------------------------------------------------
// Generic tiled SGEMM: C[M,N] = A[M,K] @ W[K,N] (+bias) (+relu)
// ---------------------------------------------------------------------------
__global__ void gemm_kernel(const float* __restrict__ A,
                            const float* __restrict__ W,
                            const float* __restrict__ bias,
                            float* __restrict__ C,
                            int M, int K, int N, int relu)
{
    __shared__ float As[16][64];
    __shared__ float Ws[16][64];

    int tid = threadIdx.x;
    int tx = tid & 15, ty = tid >> 4;
    int row0 = blockIdx.y * 64;
    int col0 = blockIdx.x * 64;

    int la_r = tid >> 2;
    int la_c = (tid & 3) * 4;
    int lw_r = tid >> 4;
    int lw_c = (tid & 15) * 4;

    float acc[4][4] = {};

    for (int kk = 0; kk < K; kk += 16) {
        float4 a4 = *(const float4*)&A[(long)(row0 + la_r)*K + kk + la_c];
        As[la_c+0][la_r] = a4.x;
        As[la_c+1][la_r] = a4.y;
        As[la_c+2][la_r] = a4.z;
        As[la_c+3][la_r] = a4.w;
        *(float4*)&Ws[lw_r][lw_c] = *(const float4*)&W[(long)(kk + lw_r)*N + col0 + lw_c];
        __syncthreads();
        #pragma unroll
        for (int k = 0; k < 16; k++) {
            float4 av = *(const float4*)&As[k][ty*4];
            float4 bv = *(const float4*)&Ws[k][tx*4];
            float a[4] = {av.x, av.y, av.z, av.w};
            float b[4] = {bv.x, bv.y, bv.z, bv.w};
            #pragma unroll
            for (int i = 0; i < 4; i++) {
                #pragma unroll
                for (int j = 0; j < 4; j++) {
                    acc[i][j] = fmaf(a[i], b[j], acc[i][j]);
                }
            }
        }
        __syncthreads();
    }

    #pragma unroll
    for (int i = 0; i < 4; i++) {
        long r = row0 + ty*4 + i;
        #pragma unroll
        for (int j = 0; j < 4; j++) {
            int c = col0 + tx*4 + j;
            float v = acc[i][j];
            if (bias) v += bias[c];
            if (relu) v = fmaxf(v, 0.0f);
            C[r*N + c] = v;
        }
    }
}

// ---------------------------------------------------------------------------
// Rope + split: qkv (TOK,768) -> bf16 Q,K,V in natural (bh, n, 32) layout.
// Q gets 1/sqrt(DH) folded in.
// ---------------------------------------------------------------------------
__global__ void rope_kernel(const float* __restrict__ qkv,
                            const float* __restrict__ rope,
                            __nv_bfloat16* __restrict__ Q,
                            __nv_bfloat16* __restrict__ K,
                            __nv_bfloat16* __restrict__ V)
{
    int t = blockIdx.x;             // token 0..8191
    int tid = threadIdx.x;          // h*32 + d
    int hh = tid >> 5, d = tid & 31;
    int b = t >> 11, n = t & 2047;

    const float* base = qkv + (long)t*768;
    float qv = base[tid];
    float kv = base[256 + tid];
    float vv = base[512 + tid];

    int axis = d >> 4;
    int dd = d & 15;
    int i = dd & 7;
    const float* rp = rope + t*32 + axis*16;
    float c = rp[i], s = rp[8 + i];

    float q2, k2;
    if (dd < 8) {
        float qy = base[tid + 8], ky = base[256 + tid + 8];
        q2 = qv*c - qy*s;
        k2 = kv*c - ky*s;
    } else {
        float qx = base[tid - 8], kx = base[256 + tid - 8];
        q2 = qx*s + qv*c;
        k2 = kx*s + kv*c;
    }

    int bh = b*HH + hh;
    long o = (((long)bh)*NN + n)*DH + d;
    Q[o] = __float2bfloat16(q2 * QK_SCALE);
    K[o] = __float2bfloat16(k2);
    V[o] = __float2bfloat16(vv);
}

// ---------------------------------------------------------------------------
// Flash attention, bf16 tensor cores (mma.sync m16n8k16), fp32 accumulate.
// Block: 64 queries, 128 threads (4 warps, 16 query rows per warp).
// Key tiles of 64. Q/K/V in (bh, n, 32) bf16.
// Output fp32 in merged-head (token, 256) layout.
// ---------------------------------------------------------------------------
__global__ __launch_bounds__(128) void attn_kernel(
    const __nv_bfloat16* __restrict__ Q,
    const __nv_bfloat16* __restrict__ K,
    const __nv_bfloat16* __restrict__ V,
    float* __restrict__ O)
{
    __shared__ __nv_bfloat16 Qs[64][40];
    __shared__ __nv_bfloat16 Ks[64][40];
    __shared__ __nv_bfloat16 Vs[64][40];

    int bh = blockIdx.y;
    int qb = blockIdx.x;
    int tid = threadIdx.x;
    int w = tid >> 5;
    int lane = tid & 31;

    const __nv_bfloat16* qg = Q + ((long)bh*NN + (long)qb*64)*DH;
    const __nv_bfloat16* kg = K + (long)bh*NN*DH;
    const __nv_bfloat16* vg = V + (long)bh*NN*DH;

    // load Q tile (64 rows x 32 d), 8 bf16 per thread per iter
    #pragma unroll
    for (int it = 0; it < 2; it++) {
        int i = tid + it*128;
        int r = i >> 2;
        int c = (i & 3)*8;
        *(uint4*)&Qs[r][c] = *(const uint4*)&qg[r*DH + c];
    }
    __syncthreads();

    // Q a-fragments: 2 k-chunks (d 0..15 and 16..31)
    unsigned qa0[4], qa1[4];
    ldsm_x4(qa0[0], qa0[1], qa0[2], qa0[3],
            smem_u32(&Qs[w*16 + (lane & 15)][(lane >> 4)*8]));
    ldsm_x4(qa1[0], qa1[1], qa1[2], qa1[3],
            smem_u32(&Qs[w*16 + (lane & 15)][16 + (lane >> 4)*8]));

    float m0 = -1e30f, m1 = -1e30f, l0 = 0.0f, l1 = 0.0f;
    float oa[4][4];
    #pragma unroll
    for (int dn = 0; dn < 4; dn++) {
        oa[dn][0] = 0.0f; oa[dn][1] = 0.0f; oa[dn][2] = 0.0f; oa[dn][3] = 0.0f;
    }

    for (int kt = 0; kt < NN; kt += 64) {
        __syncthreads();
        #pragma unroll
        for (int it = 0; it < 2; it++) {
            int i = tid + it*128;
            int r = i >> 2;
            int c = (i & 3)*8;
            *(uint4*)&Ks[r][c] = *(const uint4*)&kg[(long)(kt + r)*DH + c];
            *(uint4*)&Vs[r][c] = *(const uint4*)&vg[(long)(kt + r)*DH + c];
        }
        __syncthreads();

        // S = Q @ K^T : 8 key n-tiles of 8, 2 k-chunks each
        float sc[8][4];
        #pragma unroll
        for (int j = 0; j < 8; j++) {
            sc[j][0] = 0.0f; sc[j][1] = 0.0f; sc[j][2] = 0.0f; sc[j][3] = 0.0f;
        }
        #pragma unroll
        for (int j = 0; j < 8; j++) {
            unsigned b0, b1;
            ldsm_x2(b0, b1, smem_u32(&Ks[j*8 + (lane & 7)][((lane >> 3) & 1)*8]));
            mma_bf16(sc[j][0], sc[j][1], sc[j][2], sc[j][3],
                     qa0[0], qa0[1], qa0[2], qa0[3], b0, b1);
            ldsm_x2(b0, b1, smem_u32(&Ks[j*8 + (lane & 7)][16 + ((lane >> 3) & 1)*8]));
            mma_bf16(sc[j][0], sc[j][1], sc[j][2], sc[j][3],
                     qa1[0], qa1[1], qa1[2], qa1[3], b0, b1);
        }

        // online softmax; thread owns rows r0 = w*16+lane/4 and r0+8
        float mx0 = -1e30f, mx1 = -1e30f;
        #pragma unroll
        for (int j = 0; j < 8; j++) {
            mx0 = fmaxf(mx0, fmaxf(sc[j][0], sc[j][1]));
            mx1 = fmaxf(mx1, fmaxf(sc[j][2], sc[j][3]));
        }
        mx0 = fmaxf(mx0, __shfl_xor_sync(0xffffffffu, mx0, 1));
        mx0 = fmaxf(mx0, __shfl_xor_sync(0xffffffffu, mx0, 2));
        mx1 = fmaxf(mx1, __shfl_xor_sync(0xffffffffu, mx1, 1));
        mx1 = fmaxf(mx1, __shfl_xor_sync(0xffffffffu, mx1, 2));
        float mn0 = fmaxf(m0, mx0);
        float mn1 = fmaxf(m1, mx1);
        float corr0 = __expf(m0 - mn0);
        float corr1 = __expf(m1 - mn1);
        m0 = mn0; m1 = mn1;
        l0 *= corr0; l1 *= corr1;
        #pragma unroll
        for (int dn = 0; dn < 4; dn++) {
            oa[dn][0] *= corr0; oa[dn][1] *= corr0;
            oa[dn][2] *= corr1; oa[dn][3] *= corr1;
        }

        // P = exp(S - m), packed straight into bf16 a-fragments.
        // NOTE: l0/l1 accumulate only this lane's 16 columns; the quad-group
        // partial sums are combined once in the epilogue (corr is uniform
        // across the quad, so partials evolve linearly).
        unsigned pa[4][4];
        float ls0 = 0.0f, ls1 = 0.0f;
        #pragma unroll
        for (int j = 0; j < 8; j++) {
            float p0 = __expf(sc[j][0] - mn0);
            float p1 = __expf(sc[j][1] - mn0);
            float p2 = __expf(sc[j][2] - mn1);
            float p3 = __expf(sc[j][3] - mn1);
            ls0 += p0 + p1;
            ls1 += p2 + p3;
            pa[j >> 1][(j & 1)*2 + 0] = pack_bf16x2(p0, p1);
            pa[j >> 1][(j & 1)*2 + 1] = pack_bf16x2(p2, p3);
        }
        l0 += ls0; l1 += ls1;

        // O += P @ V : 4 key k-chunks x 4 d n-tiles
        #pragma unroll
        for (int kc = 0; kc < 4; kc++) {
            #pragma unroll
            for (int dn = 0; dn < 4; dn++) {
                unsigned b0, b1;
                ldsm_x2_t(b0, b1, smem_u32(&Vs[kc*16 + (lane & 15)][dn*8]));
                mma_bf16(oa[dn][0], oa[dn][1], oa[dn][2], oa[dn][3],
                         pa[kc][0], pa[kc][1], pa[kc][2], pa[kc][3], b0, b1);
            }
        }
    }

    // FIX (R4 bug): combine the quad-group partial softmax denominators.
    l0 += __shfl_xor_sync(0xffffffffu, l0, 1);
    l0 += __shfl_xor_sync(0xffffffffu, l0, 2);
    l1 += __shfl_xor_sync(0xffffffffu, l1, 1);
    l1 += __shfl_xor_sync(0xffffffffu, l1, 2);

    // epilogue: normalize + merged-head store
    int b = bh >> 3;
    int hh = bh & 7;
    int q0 = qb*64 + w*16 + (lane >> 2);
    float inv0 = 1.0f / l0;
    float inv1 = 1.0f / l1;
    #pragma unroll
    for (int dn = 0; dn < 4; dn++) {
        int col = hh*DH + dn*8 + (lane & 3)*2;
        float* o0 = &O[((long)b*NN + q0)*DD + col];
        o0[0] = oa[dn][0]*inv0;
        o0[1] = oa[dn][1]*inv0;
        float* o1 = &O[((long)b*NN + q0 + 8)*DD + col];
        o1[0] = oa[dn][2]*inv1;
        o1[1] = oa[dn][3]*inv1;
    }
}

// ---------------------------------------------------------------------------
// h = LayerNorm(h + r) * g + b      (block per token, 256 threads)
// ---------------------------------------------------------------------------
__global__ void add_ln_kernel(float* __restrict__ h,
                              const float* __restrict__ r,
                              const float* __restrict__ g,
                              const float* __restrict__ bta)
{
    int t = blockIdx.x, d = threadIdx.x;
    __shared__ float red[8];

    float x = h[(long)t*DD + d] + r[(long)t*DD + d];

    float s = x;
    #pragma unroll
    for (int o = 16; o > 0; o >>= 1) s += __shfl_xor_sync(0xffffffffu, s, o);
    if ((d & 31) == 0) red[d >> 5] = s;
    __syncthreads();
    float tot = 0.0f;
    #pragma unroll
    for (int i = 0; i < 8; i++) tot += red[i];
    float mean = tot * (1.0f/256.0f);
    float dx = x - mean;
    __syncthreads();

    float s2 = dx*dx;
    #pragma unroll
    for (int o = 16; o > 0; o >>= 1) s2 += __shfl_xor_sync(0xffffffffu, s2, o);
    if ((d & 31) == 0) red[d >> 5] = s2;
    __syncthreads();
    float ssq = 0.0f;
    #pragma unroll
    for (int i = 0; i < 8; i++) ssq += red[i];
    float var = ssq * (1.0f/256.0f);

    h[(long)t*DD + d] = dx * rsqrtf(var + LN_EPS) * g[d] + bta[d];
}

// ---------------------------------------------------------------------------
// Launcher
// ---------------------------------------------------------------------------
extern "C" void kernel_launch(void* const* d_in, const int* in_sizes, int n_in,
                              void* d_out, int out_size)
{
    const float* h_in    = (const float*)d_in[0];
    const float* pos     = (const float*)d_in[1];
    const float* proj_w  = (const float*)d_in[2];
    const float* proj_b  = (const float*)d_in[3];
    const float* qkv_w   = (const float*)d_in[4];
    const float* out_w   = (const float*)d_in[5];
    const float* out_b   = (const float*)d_in[6];
    const float* O_w     = (const float*)d_in[7];
    const float* O_b     = (const float*)d_in[8];
    const float* ffn1_w  = (const float*)d_in[9];
    const float* ffn1_b  = (const float*)d_in[10];
    const float* ffn2_w  = (const float*)d_in[11];
    const float* ffn2_b  = (const float*)d_in[12];
    const float* ln1_g   = (const float*)d_in[13];
    const float* ln1_b   = (const float*)d_in[14];
    const float* ln2_g   = (const float*)d_in[15];
    const float* ln2_b   = (const float*)d_in[16];
    const float* final_w = (const float*)d_in[17];

    float* h;
    float* qkv;
    float* o;
    float* t1;
    float* t2;
    float* rope;
    __nv_bfloat16* q;
    __nv_bfloat16* k;
    __nv_bfloat16* v;
    cudaGetSymbolAddress((void**)&h,    g_h);
    cudaGetSymbolAddress((void**)&qkv,  g_qkv);
    cudaGetSymbolAddress((void**)&q,    g_q);
    cudaGetSymbolAddress((void**)&k,    g_k);
    cudaGetSymbolAddress((void**)&v,    g_v);
    cudaGetSymbolAddress((void**)&o,    g_o);
    cudaGetSymbolAddress((void**)&t1,   g_t1);
    cudaGetSymbolAddress((void**)&t2,   g_t2);
    cudaGetSymbolAddress((void**)&rope, g_rope);

    proj_rope_init<<<TOK, 256>>>(h_in, pos, proj_w, proj_b, h, rope);

    for (int l = 0; l < LL; l++) {
        gemm_kernel<<<dim3(12, 128), 256>>>(h, qkv_w + (long)l*DD*3*DD, nullptr,
                                            qkv, TOK, DD, 3*DD, 0);
        rope_kernel<<<TOK, 256>>>(qkv, rope, q, k, v);
        attn_kernel<<<dim3(NN/64, BB*HH), 128>>>(q, k, v, o);
        gemm_kernel<<<dim3(4, 128), 256>>>(o, out_w + (long)l*DD*DD, out_b + l*DD,
                                           t2, TOK, DD, DD, 0);
        gemm_kernel<<<dim3(4, 128), 256>>>(t2, O_w + (long)l*DD*DD, O_b + l*DD,
                                           o, TOK, DD, DD, 0);
        add_ln_kernel<<<TOK, 256>>>(h, o, ln1_g + l*DD, ln1_b + l*DD);
        gemm_kernel<<<dim3(8, 128), 256>>>(h, ffn1_w + (long)l*DD*2*DD, ffn1_b + l*2*DD,
                                           t1, TOK, DD, 2*DD, 1);
        gemm_kernel<<<dim3(4, 128), 256>>>(t1, ffn2_w + (long)l*2*DD*DD, ffn2_b + l*DD,
                                           o, TOK, 2*DD, DD, 0);
        add_ln_kernel<<<TOK, 256>>>(h, o, ln2_g + l*DD, ln2_b + l*DD);
    }

    gemm_kernel<<<dim3(4, 128), 256>>>(h, final_w, nullptr,
                                       (float*)d_out, TOK, DD, DD, 0);
}

// round 7
// speedup vs baseline: 8.8112x; 1.8374x over previous
#include <cuda_runtime.h>
#include <cuda_bf16.h>
#include <cstdint>

// ---------------------------------------------------------------------------
// Problem constants
// ---------------------------------------------------------------------------
#define BB 4
#define NN 2048
#define TOK (BB*NN)        // 8192
#define DD 256
#define HH 8
#define DH 32
#define LL 4
#define QK_SCALE 0.17677669529663687f   // 32^-0.5
#define LN_EPS 1e-5f

// ---------------------------------------------------------------------------
// Scratch (no allocation allowed -> __device__ globals)
// ---------------------------------------------------------------------------
__device__ float g_h  [TOK*DD];
__device__ float g_qkv[TOK*3*DD];
__device__ __align__(16) __nv_bfloat16 g_q[TOK*DD];   // (bh, n, d) bf16
__device__ __align__(16) __nv_bfloat16 g_k[TOK*DD];   // (bh, n, d) bf16
__device__ __align__(16) __nv_bfloat16 g_v[TOK*DD];   // (bh, n, d) bf16
__device__ float g_o  [TOK*DD];
__device__ float g_t1 [TOK*2*DD];
__device__ float g_t2 [TOK*DD];
__device__ float g_rope[TOK*32];   // per token: [axis(2)][cos x8 | sin x8]

// ---------------------------------------------------------------------------
// PTX helpers
// ---------------------------------------------------------------------------
__device__ __forceinline__ unsigned smem_u32(const void* p)
{
    return (unsigned)__cvta_generic_to_shared(p);
}

__device__ __forceinline__ void ldsm_x4(unsigned& r0, unsigned& r1,
                                        unsigned& r2, unsigned& r3, unsigned a)
{
    asm volatile("ldmatrix.sync.aligned.m8n8.x4.shared.b16 {%0,%1,%2,%3}, [%4];"
        : "=r"(r0), "=r"(r1), "=r"(r2), "=r"(r3) : "r"(a));
}

__device__ __forceinline__ void ldsm_x2(unsigned& r0, unsigned& r1, unsigned a)
{
    asm volatile("ldmatrix.sync.aligned.m8n8.x2.shared.b16 {%0,%1}, [%2];"
        : "=r"(r0), "=r"(r1) : "r"(a));
}

__device__ __forceinline__ void ldsm_x2_t(unsigned& r0, unsigned& r1, unsigned a)
{
    asm volatile("ldmatrix.sync.aligned.m8n8.x2.trans.shared.b16 {%0,%1}, [%2];"
        : "=r"(r0), "=r"(r1) : "r"(a));
}

__device__ __forceinline__ void mma_bf16(float& c0, float& c1, float& c2, float& c3,
                                         unsigned a0, unsigned a1, unsigned a2, unsigned a3,
                                         unsigned b0, unsigned b1)
{
    asm volatile("mma.sync.aligned.m16n8k16.row.col.f32.bf16.bf16.f32 "
        "{%0,%1,%2,%3}, {%4,%5,%6,%7}, {%8,%9}, {%0,%1,%2,%3};"
        : "+f"(c0), "+f"(c1), "+f"(c2), "+f"(c3)
        : "r"(a0), "r"(a1), "r"(a2), "r"(a3), "r"(b0), "r"(b1));
}

__device__ __forceinline__ void mma_tf32(float& c0, float& c1, float& c2, float& c3,
                                         unsigned a0, unsigned a1, unsigned a2, unsigned a3,
                                         unsigned b0, unsigned b1)
{
    asm volatile("mma.sync.aligned.m16n8k8.row.col.f32.tf32.tf32.f32 "
        "{%0,%1,%2,%3}, {%4,%5,%6,%7}, {%8,%9}, {%0,%1,%2,%3};"
        : "+f"(c0), "+f"(c1), "+f"(c2), "+f"(c3)
        : "r"(a0), "r"(a1), "r"(a2), "r"(a3), "r"(b0), "r"(b1));
}

__device__ __forceinline__ unsigned pack_bf16x2(float lo, float hi)
{
    __nv_bfloat162 t = __floats2bfloat162_rn(lo, hi);
    unsigned u;
    memcpy(&u, &t, 4);
    return u;
}

// round-to-nearest fp32 -> tf32 (result is an fp32 bit-pattern with low 13 bits 0)
__device__ __forceinline__ float f2tf32(float x)
{
    unsigned r;
    asm("cvt.rna.tf32.f32 %0, %1;" : "=r"(r) : "f"(x));
    return __uint_as_float(r);
}

// ---------------------------------------------------------------------------
// Kernel 0: input projection (IN_DIM=1 outer product) + rope table
// ---------------------------------------------------------------------------
__global__ void proj_rope_init(const float* __restrict__ h_in,
                               const float* __restrict__ pos,
                               const float* __restrict__ pw,
                               const float* __restrict__ pb,
                               float* __restrict__ h,
                               float* __restrict__ rope)
{
    int t = blockIdx.x;
    int d = threadIdx.x;
    h[t*DD + d] = h_in[t]*pw[d] + pb[d];
    if (d < 16) {
        int axis = d >> 3, i = d & 7;
        float freq = exp2f(-(float)i * (13.287712379549449f / 8.0f));
        float ang = pos[t*2 + axis] * 64.0f * freq;
        float s, c;
        sincosf(ang, &s, &c);
        rope[t*32 + axis*16 + i]     = c;
        rope[t*32 + axis*16 + 8 + i] = s;
    }
}

// ---------------------------------------------------------------------------
// tf32 tensor-core GEMM: C[M,N](fp32) = A[M,K](fp32) @ W[K,N](fp32)
// BM=128, BN=128, BK=32, 256 threads = 8 warps (4M x 2N), warp tile 32x64.
// Both operands rounded fp32->tf32 (rna) during smem staging.
// A smem columns permuted within each k8 group so the (t, t+4) fragment
// pair is a single LDS.64. Pads (40 / 136) keep fragment loads conflict-free.
// ---------------------------------------------------------------------------
__global__ __launch_bounds__(256) void gemm_tf32(
    const float* __restrict__ A,
    const float* __restrict__ W,
    const float* __restrict__ bias,
    float* __restrict__ C,
    int M, int K, int N, int relu)
{
    __shared__ float As[128][40];    // [m][k-permuted]
    __shared__ float Ws[32][136];    // [k][n]

    int tid = threadIdx.x;
    int w = tid >> 5, lane = tid & 31;
    int wm = w >> 1, wn = w & 1;     // warp grid 4(M) x 2(N); warp tile 32x64
    int row0 = blockIdx.y * 128;
    int col0 = blockIdx.x * 128;

    float c[2][8][4];
    #pragma unroll
    for (int mt = 0; mt < 2; mt++)
        #pragma unroll
        for (int nt = 0; nt < 8; nt++)
            #pragma unroll
            for (int r = 0; r < 4; r++)
                c[mt][nt][r] = 0.0f;

    for (int kk = 0; kk < K; kk += 32) {
        __syncthreads();
        // stage A: 128x32, fp32 -> tf32, column-permuted within k8 groups
        #pragma unroll
        for (int it = 0; it < 4; it++) {
            int f = tid + it*256;           // 0..1023
            int r = f >> 3;                 // 0..127
            int c4 = (f & 7)*4;             // 0,4,..,28
            float4 v = *(const float4*)&A[(long)(row0 + r)*K + kk + c4];
            float vv[4] = {v.x, v.y, v.z, v.w};
            #pragma unroll
            for (int j = 0; j < 4; j++) {
                int cc = c4 + j;
                int lg = cc & 7;
                int phys = (cc & ~7) + (lg & 3)*2 + (lg >> 2);
                As[r][phys] = f2tf32(vv[j]);
            }
        }
        // stage W: 32x128, fp32 -> tf32, straight [k][n]
        #pragma unroll
        for (int it = 0; it < 4; it++) {
            int f = tid + it*256;           // 0..1023
            int r = f >> 5;                 // k 0..31
            int n4 = (f & 31)*4;            // 0..124
            float4 v = *(const float4*)&W[(long)(kk + r)*N + col0 + n4];
            float4 o;
            o.x = f2tf32(v.x); o.y = f2tf32(v.y);
            o.z = f2tf32(v.z); o.w = f2tf32(v.w);
            *(float4*)&Ws[r][n4] = o;
        }
        __syncthreads();

        #pragma unroll
        for (int ks = 0; ks < 4; ks++) {
            // A fragments: 2 m16 tiles; (a0,a2)/(a1,a3) from LDS.64 pairs
            unsigned a[2][4];
            #pragma unroll
            for (int mt = 0; mt < 2; mt++) {
                int r = wm*32 + mt*16 + (lane >> 2);
                float2 lo = *(const float2*)&As[r][ks*8 + (lane & 3)*2];
                float2 hi = *(const float2*)&As[r + 8][ks*8 + (lane & 3)*2];
                a[mt][0] = __float_as_uint(lo.x);
                a[mt][1] = __float_as_uint(hi.x);
                a[mt][2] = __float_as_uint(lo.y);
                a[mt][3] = __float_as_uint(hi.y);
            }
            // B fragments: 8 n8 tiles
            unsigned bb[8][2];
            #pragma unroll
            for (int nt = 0; nt < 8; nt++) {
                int n = wn*64 + nt*8 + (lane >> 2);
                bb[nt][0] = __float_as_uint(Ws[ks*8 + (lane & 3)][n]);
                bb[nt][1] = __float_as_uint(Ws[ks*8 + (lane & 3) + 4][n]);
            }
            // 16 MMAs
            #pragma unroll
            for (int mt = 0; mt < 2; mt++) {
                #pragma unroll
                for (int nt = 0; nt < 8; nt++) {
                    mma_tf32(c[mt][nt][0], c[mt][nt][1], c[mt][nt][2], c[mt][nt][3],
                             a[mt][0], a[mt][1], a[mt][2], a[mt][3],
                             bb[nt][0], bb[nt][1]);
                }
            }
        }
    }

    // epilogue
    #pragma unroll
    for (int mt = 0; mt < 2; mt++) {
        #pragma unroll
        for (int nt = 0; nt < 8; nt++) {
            int row = row0 + wm*32 + mt*16 + (lane >> 2);
            int col = col0 + wn*64 + nt*8 + (lane & 3)*2;
            float v0 = c[mt][nt][0];
            float v1 = c[mt][nt][1];
            float v2 = c[mt][nt][2];
            float v3 = c[mt][nt][3];
            if (bias) {
                float b0 = bias[col], b1 = bias[col + 1];
                v0 += b0; v1 += b1; v2 += b0; v3 += b1;
            }
            if (relu) {
                v0 = fmaxf(v0, 0.0f); v1 = fmaxf(v1, 0.0f);
                v2 = fmaxf(v2, 0.0f); v3 = fmaxf(v3, 0.0f);
            }
            float2 p0; p0.x = v0; p0.y = v1;
            float2 p1; p1.x = v2; p1.y = v3;
            *(float2*)&C[(long)row*N + col] = p0;
            *(float2*)&C[(long)(row + 8)*N + col] = p1;
        }
    }
}

// ---------------------------------------------------------------------------
// Rope + split: qkv (TOK,768) -> bf16 Q,K,V in natural (bh, n, 32) layout.
// ---------------------------------------------------------------------------
__global__ void rope_kernel(const float* __restrict__ qkv,
                            const float* __restrict__ rope,
                            __nv_bfloat16* __restrict__ Q,
                            __nv_bfloat16* __restrict__ K,
                            __nv_bfloat16* __restrict__ V)
{
    int t = blockIdx.x;             // token 0..8191
    int tid = threadIdx.x;          // h*32 + d
    int hh = tid >> 5, d = tid & 31;
    int b = t >> 11, n = t & 2047;

    const float* base = qkv + (long)t*768;
    float qv = base[tid];
    float kv = base[256 + tid];
    float vv = base[512 + tid];

    int axis = d >> 4;
    int dd = d & 15;
    int i = dd & 7;
    const float* rp = rope + t*32 + axis*16;
    float c = rp[i], s = rp[8 + i];

    float q2, k2;
    if (dd < 8) {
        float qy = base[tid + 8], ky = base[256 + tid + 8];
        q2 = qv*c - qy*s;
        k2 = kv*c - ky*s;
    } else {
        float qx = base[tid - 8], kx = base[256 + tid - 8];
        q2 = qx*s + qv*c;
        k2 = kx*s + kv*c;
    }

    int bh = b*HH + hh;
    long o = (((long)bh)*NN + n)*DH + d;
    Q[o] = __float2bfloat16(q2 * QK_SCALE);
    K[o] = __float2bfloat16(k2);
    V[o] = __float2bfloat16(vv);
}

// ---------------------------------------------------------------------------
// Flash attention, bf16 tensor cores (mma.sync m16n8k16), fp32 accumulate.
// (unchanged from R5 -- verified correct)
// ---------------------------------------------------------------------------
__global__ __launch_bounds__(128) void attn_kernel(
    const __nv_bfloat16* __restrict__ Q,
    const __nv_bfloat16* __restrict__ K,
    const __nv_bfloat16* __restrict__ V,
    float* __restrict__ O)
{
    __shared__ __nv_bfloat16 Qs[64][40];
    __shared__ __nv_bfloat16 Ks[64][40];
    __shared__ __nv_bfloat16 Vs[64][40];

    int bh = blockIdx.y;
    int qb = blockIdx.x;
    int tid = threadIdx.x;
    int w = tid >> 5;
    int lane = tid & 31;

    const __nv_bfloat16* qg = Q + ((long)bh*NN + (long)qb*64)*DH;
    const __nv_bfloat16* kg = K + (long)bh*NN*DH;
    const __nv_bfloat16* vg = V + (long)bh*NN*DH;

    #pragma unroll
    for (int it = 0; it < 2; it++) {
        int i = tid + it*128;
        int r = i >> 2;
        int c = (i & 3)*8;
        *(uint4*)&Qs[r][c] = *(const uint4*)&qg[r*DH + c];
    }
    __syncthreads();

    unsigned qa0[4], qa1[4];
    ldsm_x4(qa0[0], qa0[1], qa0[2], qa0[3],
            smem_u32(&Qs[w*16 + (lane & 15)][(lane >> 4)*8]));
    ldsm_x4(qa1[0], qa1[1], qa1[2], qa1[3],
            smem_u32(&Qs[w*16 + (lane & 15)][16 + (lane >> 4)*8]));

    float m0 = -1e30f, m1 = -1e30f, l0 = 0.0f, l1 = 0.0f;
    float oa[4][4];
    #pragma unroll
    for (int dn = 0; dn < 4; dn++) {
        oa[dn][0] = 0.0f; oa[dn][1] = 0.0f; oa[dn][2] = 0.0f; oa[dn][3] = 0.0f;
    }

    for (int kt = 0; kt < NN; kt += 64) {
        __syncthreads();
        #pragma unroll
        for (int it = 0; it < 2; it++) {
            int i = tid + it*128;
            int r = i >> 2;
            int c = (i & 3)*8;
            *(uint4*)&Ks[r][c] = *(const uint4*)&kg[(long)(kt + r)*DH + c];
            *(uint4*)&Vs[r][c] = *(const uint4*)&vg[(long)(kt + r)*DH + c];
        }
        __syncthreads();

        float sc[8][4];
        #pragma unroll
        for (int j = 0; j < 8; j++) {
            sc[j][0] = 0.0f; sc[j][1] = 0.0f; sc[j][2] = 0.0f; sc[j][3] = 0.0f;
        }
        #pragma unroll
        for (int j = 0; j < 8; j++) {
            unsigned b0, b1;
            ldsm_x2(b0, b1, smem_u32(&Ks[j*8 + (lane & 7)][((lane >> 3) & 1)*8]));
            mma_bf16(sc[j][0], sc[j][1], sc[j][2], sc[j][3],
                     qa0[0], qa0[1], qa0[2], qa0[3], b0, b1);
            ldsm_x2(b0, b1, smem_u32(&Ks[j*8 + (lane & 7)][16 + ((lane >> 3) & 1)*8]));
            mma_bf16(sc[j][0], sc[j][1], sc[j][2], sc[j][3],
                     qa1[0], qa1[1], qa1[2], qa1[3], b0, b1);
        }

        float mx0 = -1e30f, mx1 = -1e30f;
        #pragma unroll
        for (int j = 0; j < 8; j++) {
            mx0 = fmaxf(mx0, fmaxf(sc[j][0], sc[j][1]));
            mx1 = fmaxf(mx1, fmaxf(sc[j][2], sc[j][3]));
        }
        mx0 = fmaxf(mx0, __shfl_xor_sync(0xffffffffu, mx0, 1));
        mx0 = fmaxf(mx0, __shfl_xor_sync(0xffffffffu, mx0, 2));
        mx1 = fmaxf(mx1, __shfl_xor_sync(0xffffffffu, mx1, 1));
        mx1 = fmaxf(mx1, __shfl_xor_sync(0xffffffffu, mx1, 2));
        float mn0 = fmaxf(m0, mx0);
        float mn1 = fmaxf(m1, mx1);
        float corr0 = __expf(m0 - mn0);
        float corr1 = __expf(m1 - mn1);
        m0 = mn0; m1 = mn1;
        l0 *= corr0; l1 *= corr1;
        #pragma unroll
        for (int dn = 0; dn < 4; dn++) {
            oa[dn][0] *= corr0; oa[dn][1] *= corr0;
            oa[dn][2] *= corr1; oa[dn][3] *= corr1;
        }

        unsigned pa[4][4];
        float ls0 = 0.0f, ls1 = 0.0f;
        #pragma unroll
        for (int j = 0; j < 8; j++) {
            float p0 = __expf(sc[j][0] - mn0);
            float p1 = __expf(sc[j][1] - mn0);
            float p2 = __expf(sc[j][2] - mn1);
            float p3 = __expf(sc[j][3] - mn1);
            ls0 += p0 + p1;
            ls1 += p2 + p3;
            pa[j >> 1][(j & 1)*2 + 0] = pack_bf16x2(p0, p1);
            pa[j >> 1][(j & 1)*2 + 1] = pack_bf16x2(p2, p3);
        }
        l0 += ls0; l1 += ls1;

        #pragma unroll
        for (int kc = 0; kc < 4; kc++) {
            #pragma unroll
            for (int dn = 0; dn < 4; dn++) {
                unsigned b0, b1;
                ldsm_x2_t(b0, b1, smem_u32(&Vs[kc*16 + (lane & 15)][dn*8]));
                mma_bf16(oa[dn][0], oa[dn][1], oa[dn][2], oa[dn][3],
                         pa[kc][0], pa[kc][1], pa[kc][2], pa[kc][3], b0, b1);
            }
        }
    }

    l0 += __shfl_xor_sync(0xffffffffu, l0, 1);
    l0 += __shfl_xor_sync(0xffffffffu, l0, 2);
    l1 += __shfl_xor_sync(0xffffffffu, l1, 1);
    l1 += __shfl_xor_sync(0xffffffffu, l1, 2);

    int b = bh >> 3;
    int hh = bh & 7;
    int q0 = qb*64 + w*16 + (lane >> 2);
    float inv0 = 1.0f / l0;
    float inv1 = 1.0f / l1;
    #pragma unroll
    for (int dn = 0; dn < 4; dn++) {
        int col = hh*DH + dn*8 + (lane & 3)*2;
        float* o0 = &O[((long)b*NN + q0)*DD + col];
        o0[0] = oa[dn][0]*inv0;
        o0[1] = oa[dn][1]*inv0;
        float* o1 = &O[((long)b*NN + q0 + 8)*DD + col];
        o1[0] = oa[dn][2]*inv1;
        o1[1] = oa[dn][3]*inv1;
    }
}

// ---------------------------------------------------------------------------
// h = LayerNorm(h + r) * g + b      (block per token, 256 threads)
// ---------------------------------------------------------------------------
__global__ void add_ln_kernel(float* __restrict__ h,
                              const float* __restrict__ r,
                              const float* __restrict__ g,
                              const float* __restrict__ bta)
{
    int t = blockIdx.x, d = threadIdx.x;
    __shared__ float red[8];

    float x = h[(long)t*DD + d] + r[(long)t*DD + d];

    float s = x;
    #pragma unroll
    for (int o = 16; o > 0; o >>= 1) s += __shfl_xor_sync(0xffffffffu, s, o);
    if ((d & 31) == 0) red[d >> 5] = s;
    __syncthreads();
    float tot = 0.0f;
    #pragma unroll
    for (int i = 0; i < 8; i++) tot += red[i];
    float mean = tot * (1.0f/256.0f);
    float dx = x - mean;
    __syncthreads();

    float s2 = dx*dx;
    #pragma unroll
    for (int o = 16; o > 0; o >>= 1) s2 += __shfl_xor_sync(0xffffffffu, s2, o);
    if ((d & 31) == 0) red[d >> 5] = s2;
    __syncthreads();
    float ssq = 0.0f;
    #pragma unroll
    for (int i = 0; i < 8; i++) ssq += red[i];
    float var = ssq * (1.0f/256.0f);

    h[(long)t*DD + d] = dx * rsqrtf(var + LN_EPS) * g[d] + bta[d];
}

// ---------------------------------------------------------------------------
// Launcher
// ---------------------------------------------------------------------------
extern "C" void kernel_launch(void* const* d_in, const int* in_sizes, int n_in,
                              void* d_out, int out_size)
{
    const float* h_in    = (const float*)d_in[0];
    const float* pos     = (const float*)d_in[1];
    const float* proj_w  = (const float*)d_in[2];
    const float* proj_b  = (const float*)d_in[3];
    const float* qkv_w   = (const float*)d_in[4];
    const float* out_w   = (const float*)d_in[5];
    const float* out_b   = (const float*)d_in[6];
    const float* O_w     = (const float*)d_in[7];
    const float* O_b     = (const float*)d_in[8];
    const float* ffn1_w  = (const float*)d_in[9];
    const float* ffn1_b  = (const float*)d_in[10];
    const float* ffn2_w  = (const float*)d_in[11];
    const float* ffn2_b  = (const float*)d_in[12];
    const float* ln1_g   = (const float*)d_in[13];
    const float* ln1_b   = (const float*)d_in[14];
    const float* ln2_g   = (const float*)d_in[15];
    const float* ln2_b   = (const float*)d_in[16];
    const float* final_w = (const float*)d_in[17];

    float* h;
    float* qkv;
    float* o;
    float* t1;
    float* t2;
    float* rope;
    __nv_bfloat16* q;
    __nv_bfloat16* k;
    __nv_bfloat16* v;
    cudaGetSymbolAddress((void**)&h,    g_h);
    cudaGetSymbolAddress((void**)&qkv,  g_qkv);
    cudaGetSymbolAddress((void**)&q,    g_q);
    cudaGetSymbolAddress((void**)&k,    g_k);
    cudaGetSymbolAddress((void**)&v,    g_v);
    cudaGetSymbolAddress((void**)&o,    g_o);
    cudaGetSymbolAddress((void**)&t1,   g_t1);
    cudaGetSymbolAddress((void**)&t2,   g_t2);
    cudaGetSymbolAddress((void**)&rope, g_rope);

    proj_rope_init<<<TOK, 256>>>(h_in, pos, proj_w, proj_b, h, rope);

    for (int l = 0; l < LL; l++) {
        gemm_tf32<<<dim3(6, 64), 256>>>(h, qkv_w + (long)l*DD*3*DD, nullptr,
                                        qkv, TOK, DD, 3*DD, 0);
        rope_kernel<<<TOK, 256>>>(qkv, rope, q, k, v);
        attn_kernel<<<dim3(NN/64, BB*HH), 128>>>(q, k, v, o);
        gemm_tf32<<<dim3(2, 64), 256>>>(o, out_w + (long)l*DD*DD, out_b + l*DD,
                                        t2, TOK, DD, DD, 0);
        gemm_tf32<<<dim3(2, 64), 256>>>(t2, O_w + (long)l*DD*DD, O_b + l*DD,
                                        o, TOK, DD, DD, 0);
        add_ln_kernel<<<TOK, 256>>>(h, o, ln1_g + l*DD, ln1_b + l*DD);
        gemm_tf32<<<dim3(4, 64), 256>>>(h, ffn1_w + (long)l*DD*2*DD, ffn1_b + l*2*DD,
                                        t1, TOK, DD, 2*DD, 1);
        gemm_tf32<<<dim3(2, 64), 256>>>(t1, ffn2_w + (long)l*2*DD*DD, ffn2_b + l*DD,
                                        o, TOK, 2*DD, DD, 0);
        add_ln_kernel<<<TOK, 256>>>(h, o, ln2_g + l*DD, ln2_b + l*DD);
    }

    gemm_tf32<<<dim3(2, 64), 256>>>(h, final_w, nullptr,
                                    (float*)d_out, TOK, DD, DD, 0);
}

// round 8
// speedup vs baseline: 9.1786x; 1.0417x over previous
#include <cuda_runtime.h>
#include <cuda_bf16.h>
#include <cuda_fp16.h>
#include <cstdint>

// ---------------------------------------------------------------------------
// Problem constants
// ---------------------------------------------------------------------------
#define BB 4
#define NN 2048
#define TOK (BB*NN)        // 8192
#define DD 256
#define HH 8
#define DH 32
#define LL 4
#define QK_SCALE 0.17677669529663687f   // 32^-0.5
// QK_SCALE * log2(e): softmax done in base-2 domain
#define QK_SCALE_LOG2E 0.25503164244492893f
#define LN_EPS 1e-5f

// ---------------------------------------------------------------------------
// Scratch (no allocation allowed -> __device__ globals)
// ---------------------------------------------------------------------------
__device__ float g_h  [TOK*DD];
__device__ float g_qkv[TOK*3*DD];
__device__ __align__(16) __half g_q[TOK*DD];   // (bh, n, d) fp16 (pre-scaled)
__device__ __align__(16) __half g_k[TOK*DD];   // (bh, n, d) fp16
__device__ __align__(16) __half g_v[TOK*DD];   // (bh, n, d) fp16
__device__ float g_o  [TOK*DD];
__device__ float g_t1 [TOK*2*DD];
__device__ float g_t2 [TOK*DD];
__device__ float g_rope[TOK*32];   // per token: [axis(2)][cos x8 | sin x8]
__device__ float g_wc [LL*DD*DD];  // merged out_w @ O_w
__device__ float g_bc [LL*DD];     // merged out_b @ O_w + O_b

// ---------------------------------------------------------------------------
// PTX helpers
// ---------------------------------------------------------------------------
__device__ __forceinline__ unsigned smem_u32(const void* p)
{
    return (unsigned)__cvta_generic_to_shared(p);
}

__device__ __forceinline__ void ldsm_x4(unsigned& r0, unsigned& r1,
                                        unsigned& r2, unsigned& r3, unsigned a)
{
    asm volatile("ldmatrix.sync.aligned.m8n8.x4.shared.b16 {%0,%1,%2,%3}, [%4];"
        : "=r"(r0), "=r"(r1), "=r"(r2), "=r"(r3) : "r"(a));
}

__device__ __forceinline__ void ldsm_x2(unsigned& r0, unsigned& r1, unsigned a)
{
    asm volatile("ldmatrix.sync.aligned.m8n8.x2.shared.b16 {%0,%1}, [%2];"
        : "=r"(r0), "=r"(r1) : "r"(a));
}

__device__ __forceinline__ void ldsm_x2_t(unsigned& r0, unsigned& r1, unsigned a)
{
    asm volatile("ldmatrix.sync.aligned.m8n8.x2.trans.shared.b16 {%0,%1}, [%2];"
        : "=r"(r0), "=r"(r1) : "r"(a));
}

__device__ __forceinline__ void mma_f16(float& c0, float& c1, float& c2, float& c3,
                                        unsigned a0, unsigned a1, unsigned a2, unsigned a3,
                                        unsigned b0, unsigned b1)
{
    asm volatile("mma.sync.aligned.m16n8k16.row.col.f32.f16.f16.f32 "
        "{%0,%1,%2,%3}, {%4,%5,%6,%7}, {%8,%9}, {%0,%1,%2,%3};"
        : "+f"(c0), "+f"(c1), "+f"(c2), "+f"(c3)
        : "r"(a0), "r"(a1), "r"(a2), "r"(a3), "r"(b0), "r"(b1));
}

__device__ __forceinline__ void mma_tf32(float& c0, float& c1, float& c2, float& c3,
                                         unsigned a0, unsigned a1, unsigned a2, unsigned a3,
                                         unsigned b0, unsigned b1)
{
    asm volatile("mma.sync.aligned.m16n8k8.row.col.f32.tf32.tf32.f32 "
        "{%0,%1,%2,%3}, {%4,%5,%6,%7}, {%8,%9}, {%0,%1,%2,%3};"
        : "+f"(c0), "+f"(c1), "+f"(c2), "+f"(c3)
        : "r"(a0), "r"(a1), "r"(a2), "r"(a3), "r"(b0), "r"(b1));
}

// round-to-nearest fp32 -> tf32 (fp32 bit-pattern, low 13 bits 0)
__device__ __forceinline__ float f2tf32(float x)
{
    unsigned r;
    asm("cvt.rna.tf32.f32 %0, %1;" : "=r"(r) : "f"(x));
    return __uint_as_float(r);
}

__device__ __forceinline__ unsigned h2_bits(__half2 h)
{
    unsigned u;
    memcpy(&u, &h, 4);
    return u;
}

// ---------------------------------------------------------------------------
// Kernel 0: input projection (IN_DIM=1 outer product) + rope table
// ---------------------------------------------------------------------------
__global__ void proj_rope_init(const float* __restrict__ h_in,
                               const float* __restrict__ pos,
                               const float* __restrict__ pw,
                               const float* __restrict__ pb,
                               float* __restrict__ h,
                               float* __restrict__ rope)
{
    int t = blockIdx.x;
    int d = threadIdx.x;
    h[t*DD + d] = h_in[t]*pw[d] + pb[d];
    if (d < 16) {
        int axis = d >> 3, i = d & 7;
        float freq = exp2f(-(float)i * (13.287712379549449f / 8.0f));
        float ang = pos[t*2 + axis] * 64.0f * freq;
        float s, c;
        sincosf(ang, &s, &c);
        rope[t*32 + axis*16 + i]     = c;
        rope[t*32 + axis*16 + 8 + i] = s;
    }
}

// ---------------------------------------------------------------------------
// Merged bias: bc[l] = out_b[l] @ O_w[l] + O_b[l]
// ---------------------------------------------------------------------------
__global__ void bias_combine(const float* __restrict__ out_b,
                             const float* __restrict__ O_w,
                             const float* __restrict__ O_b,
                             float* __restrict__ bc)
{
    int l = blockIdx.x;
    int n = threadIdx.x;
    const float* ob = out_b + l*DD;
    const float* Ow = O_w + (long)l*DD*DD;
    float s = O_b[l*DD + n];
    for (int k2 = 0; k2 < DD; k2++)
        s += ob[k2]*Ow[k2*DD + n];
    bc[l*DD + n] = s;
}

// ---------------------------------------------------------------------------
// tf32 tensor-core GEMM: C[M,N](fp32) = A[M,K](fp32) @ W[K,N](fp32)
// BM=128, BN=128, BK=32, 256 threads = 8 warps (4M x 2N), warp tile 32x64.
// Optional batching over blockIdx.z with element strides batA/batW/batC.
// ---------------------------------------------------------------------------
__global__ __launch_bounds__(256) void gemm_tf32(
    const float* __restrict__ A,
    const float* __restrict__ W,
    const float* __restrict__ bias,
    float* __restrict__ C,
    int M, int K, int N, int relu,
    long batA, long batW, long batC)
{
    __shared__ float As[128][40];    // [m][k-permuted]
    __shared__ float Ws[32][136];    // [k][n]

    A += blockIdx.z*batA;
    W += blockIdx.z*batW;
    C += blockIdx.z*batC;

    int tid = threadIdx.x;
    int w = tid >> 5, lane = tid & 31;
    int wm = w >> 1, wn = w & 1;     // warp grid 4(M) x 2(N); warp tile 32x64
    int row0 = blockIdx.y * 128;
    int col0 = blockIdx.x * 128;

    float c[2][8][4];
    #pragma unroll
    for (int mt = 0; mt < 2; mt++)
        #pragma unroll
        for (int nt = 0; nt < 8; nt++)
            #pragma unroll
            for (int r = 0; r < 4; r++)
                c[mt][nt][r] = 0.0f;

    for (int kk = 0; kk < K; kk += 32) {
        __syncthreads();
        #pragma unroll
        for (int it = 0; it < 4; it++) {
            int f = tid + it*256;
            int r = f >> 3;
            int c4 = (f & 7)*4;
            float4 v = *(const float4*)&A[(long)(row0 + r)*K + kk + c4];
            float vv[4] = {v.x, v.y, v.z, v.w};
            #pragma unroll
            for (int j = 0; j < 4; j++) {
                int cc = c4 + j;
                int lg = cc & 7;
                int phys = (cc & ~7) + (lg & 3)*2 + (lg >> 2);
                As[r][phys] = f2tf32(vv[j]);
            }
        }
        #pragma unroll
        for (int it = 0; it < 4; it++) {
            int f = tid + it*256;
            int r = f >> 5;
            int n4 = (f & 31)*4;
            float4 v = *(const float4*)&W[(long)(kk + r)*N + col0 + n4];
            float4 o;
            o.x = f2tf32(v.x); o.y = f2tf32(v.y);
            o.z = f2tf32(v.z); o.w = f2tf32(v.w);
            *(float4*)&Ws[r][n4] = o;
        }
        __syncthreads();

        #pragma unroll
        for (int ks = 0; ks < 4; ks++) {
            unsigned a[2][4];
            #pragma unroll
            for (int mt = 0; mt < 2; mt++) {
                int r = wm*32 + mt*16 + (lane >> 2);
                float2 lo = *(const float2*)&As[r][ks*8 + (lane & 3)*2];
                float2 hi = *(const float2*)&As[r + 8][ks*8 + (lane & 3)*2];
                a[mt][0] = __float_as_uint(lo.x);
                a[mt][1] = __float_as_uint(hi.x);
                a[mt][2] = __float_as_uint(lo.y);
                a[mt][3] = __float_as_uint(hi.y);
            }
            unsigned bb[8][2];
            #pragma unroll
            for (int nt = 0; nt < 8; nt++) {
                int n = wn*64 + nt*8 + (lane >> 2);
                bb[nt][0] = __float_as_uint(Ws[ks*8 + (lane & 3)][n]);
                bb[nt][1] = __float_as_uint(Ws[ks*8 + (lane & 3) + 4][n]);
            }
            #pragma unroll
            for (int mt = 0; mt < 2; mt++) {
                #pragma unroll
                for (int nt = 0; nt < 8; nt++) {
                    mma_tf32(c[mt][nt][0], c[mt][nt][1], c[mt][nt][2], c[mt][nt][3],
                             a[mt][0], a[mt][1], a[mt][2], a[mt][3],
                             bb[nt][0], bb[nt][1]);
                }
            }
        }
    }

    #pragma unroll
    for (int mt = 0; mt < 2; mt++) {
        #pragma unroll
        for (int nt = 0; nt < 8; nt++) {
            int row = row0 + wm*32 + mt*16 + (lane >> 2);
            int col = col0 + wn*64 + nt*8 + (lane & 3)*2;
            float v0 = c[mt][nt][0];
            float v1 = c[mt][nt][1];
            float v2 = c[mt][nt][2];
            float v3 = c[mt][nt][3];
            if (bias) {
                float b0 = bias[col], b1 = bias[col + 1];
                v0 += b0; v1 += b1; v2 += b0; v3 += b1;
            }
            if (relu) {
                v0 = fmaxf(v0, 0.0f); v1 = fmaxf(v1, 0.0f);
                v2 = fmaxf(v2, 0.0f); v3 = fmaxf(v3, 0.0f);
            }
            float2 p0; p0.x = v0; p0.y = v1;
            float2 p1; p1.x = v2; p1.y = v3;
            *(float2*)&C[(long)row*N + col] = p0;
            *(float2*)&C[(long)(row + 8)*N + col] = p1;
        }
    }
}

// ---------------------------------------------------------------------------
// Rope + split: qkv (TOK,768) -> fp16 Q,K,V in (bh, n, 32) layout.
// Q gets QK_SCALE * log2(e) folded in (softmax runs in base-2 domain).
// ---------------------------------------------------------------------------
__global__ void rope_kernel(const float* __restrict__ qkv,
                            const float* __restrict__ rope,
                            __half* __restrict__ Q,
                            __half* __restrict__ K,
                            __half* __restrict__ V)
{
    int t = blockIdx.x;             // token 0..8191
    int tid = threadIdx.x;          // h*32 + d
    int hh = tid >> 5, d = tid & 31;
    int b = t >> 11, n = t & 2047;

    const float* base = qkv + (long)t*768;
    float qv = base[tid];
    float kv = base[256 + tid];
    float vv = base[512 + tid];

    int axis = d >> 4;
    int dd = d & 15;
    int i = dd & 7;
    const float* rp = rope + t*32 + axis*16;
    float c = rp[i], s = rp[8 + i];

    float q2, k2;
    if (dd < 8) {
        float qy = base[tid + 8], ky = base[256 + tid + 8];
        q2 = qv*c - qy*s;
        k2 = kv*c - ky*s;
    } else {
        float qx = base[tid - 8], kx = base[256 + tid - 8];
        q2 = qx*s + qv*c;
        k2 = kx*s + kv*c;
    }

    int bh = b*HH + hh;
    long o = (((long)bh)*NN + n)*DH + d;
    Q[o] = __float2half(q2 * QK_SCALE_LOG2E);
    K[o] = __float2half(k2);
    V[o] = __float2half(vv);
}

// ---------------------------------------------------------------------------
// Flash attention, fp16 tensor cores, base-2 softmax, h2exp2 (2 scores/MUFU op),
// softmax denominator accumulated by an extra ones-column in the PV mma.
// Block: 64 queries, 128 threads (4 warps). Key tiles of 64.
// ---------------------------------------------------------------------------
__global__ __launch_bounds__(128) void attn_kernel(
    const __half* __restrict__ Q,
    const __half* __restrict__ K,
    const __half* __restrict__ V,
    float* __restrict__ O)
{
    __shared__ __half Qs[64][40];
    __shared__ __half Ks[64][40];
    __shared__ __half Vs[64][40];   // cols 0..31 data, col 32 = 1.0, 33..39 = 0

    int bh = blockIdx.y;
    int qb = blockIdx.x;
    int tid = threadIdx.x;
    int w = tid >> 5;
    int lane = tid & 31;

    const __half* qg = Q + ((long)bh*NN + (long)qb*64)*DH;
    const __half* kg = K + (long)bh*NN*DH;
    const __half* vg = V + (long)bh*NN*DH;

    // load Q tile; init Vs ones-column (cols 32..39) once
    #pragma unroll
    for (int it = 0; it < 2; it++) {
        int i = tid + it*128;
        int r = i >> 2;
        int c = (i & 3)*8;
        *(uint4*)&Qs[r][c] = *(const uint4*)&qg[r*DH + c];
    }
    if (tid < 64) {
        uint4 ones;
        ones.x = 0x00003C00u;   // {1.0h, 0}
        ones.y = 0u; ones.z = 0u; ones.w = 0u;
        *(uint4*)&Vs[tid][32] = ones;
    }
    __syncthreads();

    unsigned qa0[4], qa1[4];
    ldsm_x4(qa0[0], qa0[1], qa0[2], qa0[3],
            smem_u32(&Qs[w*16 + (lane & 15)][(lane >> 4)*8]));
    ldsm_x4(qa1[0], qa1[1], qa1[2], qa1[3],
            smem_u32(&Qs[w*16 + (lane & 15)][16 + (lane >> 4)*8]));

    float m0 = -1e30f, m1 = -1e30f;
    float oa[5][4];                 // dn 0..3 = output d-tiles, dn 4 = l-column
    #pragma unroll
    for (int dn = 0; dn < 5; dn++) {
        oa[dn][0] = 0.0f; oa[dn][1] = 0.0f; oa[dn][2] = 0.0f; oa[dn][3] = 0.0f;
    }

    for (int kt = 0; kt < NN; kt += 64) {
        __syncthreads();
        #pragma unroll
        for (int it = 0; it < 2; it++) {
            int i = tid + it*128;
            int r = i >> 2;
            int c = (i & 3)*8;
            *(uint4*)&Ks[r][c] = *(const uint4*)&kg[(long)(kt + r)*DH + c];
            *(uint4*)&Vs[r][c] = *(const uint4*)&vg[(long)(kt + r)*DH + c];
        }
        __syncthreads();

        // S = Q @ K^T (scores already in log2 domain)
        float sc[8][4];
        #pragma unroll
        for (int j = 0; j < 8; j++) {
            sc[j][0] = 0.0f; sc[j][1] = 0.0f; sc[j][2] = 0.0f; sc[j][3] = 0.0f;
        }
        #pragma unroll
        for (int j = 0; j < 8; j++) {
            unsigned b0, b1;
            ldsm_x2(b0, b1, smem_u32(&Ks[j*8 + (lane & 7)][((lane >> 3) & 1)*8]));
            mma_f16(sc[j][0], sc[j][1], sc[j][2], sc[j][3],
                    qa0[0], qa0[1], qa0[2], qa0[3], b0, b1);
            ldsm_x2(b0, b1, smem_u32(&Ks[j*8 + (lane & 7)][16 + ((lane >> 3) & 1)*8]));
            mma_f16(sc[j][0], sc[j][1], sc[j][2], sc[j][3],
                    qa1[0], qa1[1], qa1[2], qa1[3], b0, b1);
        }

        // online softmax (base 2)
        float mx0 = -1e30f, mx1 = -1e30f;
        #pragma unroll
        for (int j = 0; j < 8; j++) {
            mx0 = fmaxf(mx0, fmaxf(sc[j][0], sc[j][1]));
            mx1 = fmaxf(mx1, fmaxf(sc[j][2], sc[j][3]));
        }
        mx0 = fmaxf(mx0, __shfl_xor_sync(0xffffffffu, mx0, 1));
        mx0 = fmaxf(mx0, __shfl_xor_sync(0xffffffffu, mx0, 2));
        mx1 = fmaxf(mx1, __shfl_xor_sync(0xffffffffu, mx1, 1));
        mx1 = fmaxf(mx1, __shfl_xor_sync(0xffffffffu, mx1, 2));
        float mn0 = fmaxf(m0, mx0);
        float mn1 = fmaxf(m1, mx1);
        float corr0 = exp2f(m0 - mn0);
        float corr1 = exp2f(m1 - mn1);
        m0 = mn0; m1 = mn1;
        #pragma unroll
        for (int dn = 0; dn < 5; dn++) {
            oa[dn][0] *= corr0; oa[dn][1] *= corr0;
            oa[dn][2] *= corr1; oa[dn][3] *= corr1;
        }

        // P = 2^(S - m): one h2exp2 per score pair, result IS the fp16 a-frag
        unsigned pa[4][4];
        #pragma unroll
        for (int j = 0; j < 8; j++) {
            __half2 e0 = h2exp2(__floats2half2_rn(sc[j][0] - mn0, sc[j][1] - mn0));
            __half2 e1 = h2exp2(__floats2half2_rn(sc[j][2] - mn1, sc[j][3] - mn1));
            pa[j >> 1][(j & 1)*2 + 0] = h2_bits(e0);
            pa[j >> 1][(j & 1)*2 + 1] = h2_bits(e1);
        }

        // O += P @ [V | ones]: dn 4 accumulates the softmax denominator
        #pragma unroll
        for (int kc = 0; kc < 4; kc++) {
            #pragma unroll
            for (int dn = 0; dn < 5; dn++) {
                unsigned b0, b1;
                ldsm_x2_t(b0, b1, smem_u32(&Vs[kc*16 + (lane & 15)][dn*8]));
                mma_f16(oa[dn][0], oa[dn][1], oa[dn][2], oa[dn][3],
                        pa[kc][0], pa[kc][1], pa[kc][2], pa[kc][3], b0, b1);
            }
        }
    }

    // l lives in oa[4][0] (row r0) / oa[4][2] (row r1) of the quad leader
    int src = lane & 28;
    float l0 = __shfl_sync(0xffffffffu, oa[4][0], src);
    float l1 = __shfl_sync(0xffffffffu, oa[4][2], src);

    int b = bh >> 3;
    int hh = bh & 7;
    int q0 = qb*64 + w*16 + (lane >> 2);
    float inv0 = 1.0f / l0;
    float inv1 = 1.0f / l1;
    #pragma unroll
    for (int dn = 0; dn < 4; dn++) {
        int col = hh*DH + dn*8 + (lane & 3)*2;
        float* o0 = &O[((long)b*NN + q0)*DD + col];
        o0[0] = oa[dn][0]*inv0;
        o0[1] = oa[dn][1]*inv0;
        float* o1 = &O[((long)b*NN + q0 + 8)*DD + col];
        o1[0] = oa[dn][2]*inv1;
        o1[1] = oa[dn][3]*inv1;
    }
}

// ---------------------------------------------------------------------------
// h = LayerNorm(h + r) * g + b      (block per token, 256 threads)
// ---------------------------------------------------------------------------
__global__ void add_ln_kernel(float* __restrict__ h,
                              const float* __restrict__ r,
                              const float* __restrict__ g,
                              const float* __restrict__ bta)
{
    int t = blockIdx.x, d = threadIdx.x;
    __shared__ float red[8];

    float x = h[(long)t*DD + d] + r[(long)t*DD + d];

    float s = x;
    #pragma unroll
    for (int o = 16; o > 0; o >>= 1) s += __shfl_xor_sync(0xffffffffu, s, o);
    if ((d & 31) == 0) red[d >> 5] = s;
    __syncthreads();
    float tot = 0.0f;
    #pragma unroll
    for (int i = 0; i < 8; i++) tot += red[i];
    float mean = tot * (1.0f/256.0f);
    float dx = x - mean;
    __syncthreads();

    float s2 = dx*dx;
    #pragma unroll
    for (int o = 16; o > 0; o >>= 1) s2 += __shfl_xor_sync(0xffffffffu, s2, o);
    if ((d & 31) == 0) red[d >> 5] = s2;
    __syncthreads();
    float ssq = 0.0f;
    #pragma unroll
    for (int i = 0; i < 8; i++) ssq += red[i];
    float var = ssq * (1.0f/256.0f);

    h[(long)t*DD + d] = dx * rsqrtf(var + LN_EPS) * g[d] + bta[d];
}

// ---------------------------------------------------------------------------
// Launcher
// ---------------------------------------------------------------------------
extern "C" void kernel_launch(void* const* d_in, const int* in_sizes, int n_in,
                              void* d_out, int out_size)
{
    const float* h_in    = (const float*)d_in[0];
    const float* pos     = (const float*)d_in[1];
    const float* proj_w  = (const float*)d_in[2];
    const float* proj_b  = (const float*)d_in[3];
    const float* qkv_w   = (const float*)d_in[4];
    const float* out_w   = (const float*)d_in[5];
    const float* out_b   = (const float*)d_in[6];
    const float* O_w     = (const float*)d_in[7];
    const float* O_b     = (const float*)d_in[8];
    const float* ffn1_w  = (const float*)d_in[9];
    const float* ffn1_b  = (const float*)d_in[10];
    const float* ffn2_w  = (const float*)d_in[11];
    const float* ffn2_b  = (const float*)d_in[12];
    const float* ln1_g   = (const float*)d_in[13];
    const float* ln1_b   = (const float*)d_in[14];
    const float* ln2_g   = (const float*)d_in[15];
    const float* ln2_b   = (const float*)d_in[16];
    const float* final_w = (const float*)d_in[17];

    float* h;
    float* qkv;
    float* o;
    float* t1;
    float* t2;
    float* rope;
    float* wc;
    float* bc;
    __half* q;
    __half* k;
    __half* v;
    cudaGetSymbolAddress((void**)&h,    g_h);
    cudaGetSymbolAddress((void**)&qkv,  g_qkv);
    cudaGetSymbolAddress((void**)&q,    g_q);
    cudaGetSymbolAddress((void**)&k,    g_k);
    cudaGetSymbolAddress((void**)&v,    g_v);
    cudaGetSymbolAddress((void**)&o,    g_o);
    cudaGetSymbolAddress((void**)&t1,   g_t1);
    cudaGetSymbolAddress((void**)&t2,   g_t2);
    cudaGetSymbolAddress((void**)&rope, g_rope);
    cudaGetSymbolAddress((void**)&wc,   g_wc);
    cudaGetSymbolAddress((void**)&bc,   g_bc);

    // merged out/O projection: wc[l] = out_w[l] @ O_w[l]; bc[l] = out_b[l]@O_w[l] + O_b[l]
    gemm_tf32<<<dim3(2, 2, LL), 256>>>(out_w, O_w, nullptr, wc, DD, DD, DD, 0,
                                       (long)DD*DD, (long)DD*DD, (long)DD*DD);
    bias_combine<<<LL, DD>>>(out_b, O_w, O_b, bc);

    proj_rope_init<<<TOK, 256>>>(h_in, pos, proj_w, proj_b, h, rope);

    for (int l = 0; l < LL; l++) {
        gemm_tf32<<<dim3(6, 64), 256>>>(h, qkv_w + (long)l*DD*3*DD, nullptr,
                                        qkv, TOK, DD, 3*DD, 0, 0, 0, 0);
        rope_kernel<<<TOK, 256>>>(qkv, rope, q, k, v);
        attn_kernel<<<dim3(NN/64, BB*HH), 128>>>(q, k, v, o);
        gemm_tf32<<<dim3(2, 64), 256>>>(o, wc + (long)l*DD*DD, bc + l*DD,
                                        t2, TOK, DD, DD, 0, 0, 0, 0);
        add_ln_kernel<<<TOK, 256>>>(h, t2, ln1_g + l*DD, ln1_b + l*DD);
        gemm_tf32<<<dim3(4, 64), 256>>>(h, ffn1_w + (long)l*DD*2*DD, ffn1_b + l*2*DD,
                                        t1, TOK, DD, 2*DD, 1, 0, 0, 0);
        gemm_tf32<<<dim3(2, 64), 256>>>(t1, ffn2_w + (long)l*2*DD*DD, ffn2_b + l*DD,
                                        o, TOK, 2*DD, DD, 0, 0, 0, 0);
        add_ln_kernel<<<TOK, 256>>>(h, o, ln2_g + l*DD, ln2_b + l*DD);
    }

    gemm_tf32<<<dim3(2, 64), 256>>>(h, final_w, nullptr,
                                    (float*)d_out, TOK, DD, DD, 0, 0, 0, 0);
}

// round 10
// speedup vs baseline: 10.4681x; 1.1405x over previous
#include <cuda_runtime.h>
#include <cuda_bf16.h>
#include <cuda_fp16.h>
#include <cstdint>

// ---------------------------------------------------------------------------
// Problem constants
// ---------------------------------------------------------------------------
#define BB 4
#define NN 2048
#define TOK (BB*NN)        // 8192
#define DD 256
#define HH 8
#define DH 32
#define LL 4
#define QK_SCALE 0.17677669529663687f   // 32^-0.5
#define QK_SCALE_LOG2E 0.25503164244492893f
#define LN_EPS 1e-5f

// ---------------------------------------------------------------------------
// Scratch (no allocation allowed -> __device__ globals)
// ---------------------------------------------------------------------------
__device__ float g_h  [TOK*DD];
__device__ float g_qkv[TOK*3*DD];
__device__ __align__(16) __half g_q[TOK*DD];   // (bh, n, d) fp16 (pre-scaled)
__device__ __align__(16) __half g_k[TOK*DD];   // (bh, n, d) fp16
__device__ __align__(16) __half g_v[TOK*DD];   // (bh, n, d) fp16
__device__ float g_o  [TOK*DD];
__device__ float g_t1 [TOK*2*DD];
__device__ float g_t2 [TOK*DD];
__device__ float g_rope[TOK*32];
__device__ float g_wc [LL*DD*DD];  // merged out_w @ O_w (fp32)
__device__ float g_bc [LL*DD];     // merged out_b @ O_w + O_b

// fp16 weight copies
__device__ __align__(16) __half g_qkvw_h [LL*DD*3*DD];
__device__ __align__(16) __half g_wc_h   [LL*DD*DD];
__device__ __align__(16) __half g_ffn1w_h[LL*DD*2*DD];
__device__ __align__(16) __half g_ffn2w_h[LL*2*DD*DD];
__device__ __align__(16) __half g_finw_h [DD*DD];

// ---------------------------------------------------------------------------
// PTX helpers
// ---------------------------------------------------------------------------
__device__ __forceinline__ unsigned smem_u32(const void* p)
{
    return (unsigned)__cvta_generic_to_shared(p);
}

__device__ __forceinline__ void ldsm_x4(unsigned& r0, unsigned& r1,
                                        unsigned& r2, unsigned& r3, unsigned a)
{
    asm volatile("ldmatrix.sync.aligned.m8n8.x4.shared.b16 {%0,%1,%2,%3}, [%4];"
        : "=r"(r0), "=r"(r1), "=r"(r2), "=r"(r3) : "r"(a));
}

__device__ __forceinline__ void ldsm_x4_t(unsigned& r0, unsigned& r1,
                                          unsigned& r2, unsigned& r3, unsigned a)
{
    asm volatile("ldmatrix.sync.aligned.m8n8.x4.trans.shared.b16 {%0,%1,%2,%3}, [%4];"
        : "=r"(r0), "=r"(r1), "=r"(r2), "=r"(r3) : "r"(a));
}

__device__ __forceinline__ void ldsm_x2(unsigned& r0, unsigned& r1, unsigned a)
{
    asm volatile("ldmatrix.sync.aligned.m8n8.x2.shared.b16 {%0,%1}, [%2];"
        : "=r"(r0), "=r"(r1) : "r"(a));
}

__device__ __forceinline__ void ldsm_x2_t(unsigned& r0, unsigned& r1, unsigned a)
{
    asm volatile("ldmatrix.sync.aligned.m8n8.x2.trans.shared.b16 {%0,%1}, [%2];"
        : "=r"(r0), "=r"(r1) : "r"(a));
}

__device__ __forceinline__ void mma_f16(float& c0, float& c1, float& c2, float& c3,
                                        unsigned a0, unsigned a1, unsigned a2, unsigned a3,
                                        unsigned b0, unsigned b1)
{
    asm volatile("mma.sync.aligned.m16n8k16.row.col.f32.f16.f16.f32 "
        "{%0,%1,%2,%3}, {%4,%5,%6,%7}, {%8,%9}, {%0,%1,%2,%3};"
        : "+f"(c0), "+f"(c1), "+f"(c2), "+f"(c3)
        : "r"(a0), "r"(a1), "r"(a2), "r"(a3), "r"(b0), "r"(b1));
}

__device__ __forceinline__ void mma_tf32(float& c0, float& c1, float& c2, float& c3,
                                         unsigned a0, unsigned a1, unsigned a2, unsigned a3,
                                         unsigned b0, unsigned b1)
{
    asm volatile("mma.sync.aligned.m16n8k8.row.col.f32.tf32.tf32.f32 "
        "{%0,%1,%2,%3}, {%4,%5,%6,%7}, {%8,%9}, {%0,%1,%2,%3};"
        : "+f"(c0), "+f"(c1), "+f"(c2), "+f"(c3)
        : "r"(a0), "r"(a1), "r"(a2), "r"(a3), "r"(b0), "r"(b1));
}

__device__ __forceinline__ float f2tf32(float x)
{
    unsigned r;
    asm("cvt.rna.tf32.f32 %0, %1;" : "=r"(r) : "f"(x));
    return __uint_as_float(r);
}

__device__ __forceinline__ unsigned h2_bits(__half2 h)
{
    unsigned u;
    memcpy(&u, &h, 4);
    return u;
}

__device__ __forceinline__ unsigned pack_h2(float lo, float hi)
{
    __half2 t = __floats2half2_rn(lo, hi);
    unsigned u;
    memcpy(&u, &t, 4);
    return u;
}

// ---------------------------------------------------------------------------
// Weight conversion fp32 -> fp16
// ---------------------------------------------------------------------------
__global__ void to_f16_kernel(const float* __restrict__ in,
                              __half* __restrict__ out, int n)
{
    int i = (blockIdx.x*256 + threadIdx.x)*4;
    if (i < n) {
        float4 v = *(const float4*)&in[i];
        uint2 u;
        u.x = pack_h2(v.x, v.y);
        u.y = pack_h2(v.z, v.w);
        *(uint2*)&out[i] = u;
    }
}

// ---------------------------------------------------------------------------
// Kernel 0: input projection (IN_DIM=1 outer product) + rope table
// ---------------------------------------------------------------------------
__global__ void proj_rope_init(const float* __restrict__ h_in,
                               const float* __restrict__ pos,
                               const float* __restrict__ pw,
                               const float* __restrict__ pb,
                               float* __restrict__ h,
                               float* __restrict__ rope)
{
    int t = blockIdx.x;
    int d = threadIdx.x;
    h[t*DD + d] = h_in[t]*pw[d] + pb[d];
    if (d < 16) {
        int axis = d >> 3, i = d & 7;
        float freq = exp2f(-(float)i * (13.287712379549449f / 8.0f));
        float ang = pos[t*2 + axis] * 64.0f * freq;
        float s, c;
        sincosf(ang, &s, &c);
        rope[t*32 + axis*16 + i]     = c;
        rope[t*32 + axis*16 + 8 + i] = s;
    }
}

// ---------------------------------------------------------------------------
// Merged bias: bc[l] = out_b[l] @ O_w[l] + O_b[l]
// ---------------------------------------------------------------------------
__global__ void bias_combine(const float* __restrict__ out_b,
                             const float* __restrict__ O_w,
                             const float* __restrict__ O_b,
                             float* __restrict__ bc)
{
    int l = blockIdx.x;
    int n = threadIdx.x;
    const float* ob = out_b + l*DD;
    const float* Ow = O_w + (long)l*DD*DD;
    float s = O_b[l*DD + n];
    for (int k2 = 0; k2 < DD; k2++)
        s += ob[k2]*Ow[k2*DD + n];
    bc[l*DD + n] = s;
}

// ---------------------------------------------------------------------------
// tf32 GEMM (kept for the one-time wc = out_w @ O_w precompute)
// ---------------------------------------------------------------------------
__global__ __launch_bounds__(256) void gemm_tf32(
    const float* __restrict__ A,
    const float* __restrict__ W,
    float* __restrict__ C,
    int M, int K, int N,
    long batA, long batW, long batC)
{
    __shared__ float As[128][40];
    __shared__ float Ws[32][136];

    A += blockIdx.z*batA;
    W += blockIdx.z*batW;
    C += blockIdx.z*batC;

    int tid = threadIdx.x;
    int w = tid >> 5, lane = tid & 31;
    int wm = w >> 1, wn = w & 1;
    int row0 = blockIdx.y * 128;
    int col0 = blockIdx.x * 128;

    float c[2][8][4];
    #pragma unroll
    for (int mt = 0; mt < 2; mt++)
        #pragma unroll
        for (int nt = 0; nt < 8; nt++)
            #pragma unroll
            for (int r = 0; r < 4; r++)
                c[mt][nt][r] = 0.0f;

    for (int kk = 0; kk < K; kk += 32) {
        __syncthreads();
        #pragma unroll
        for (int it = 0; it < 4; it++) {
            int f = tid + it*256;
            int r = f >> 3;
            int c4 = (f & 7)*4;
            float4 v = *(const float4*)&A[(long)(row0 + r)*K + kk + c4];
            float vv[4] = {v.x, v.y, v.z, v.w};
            #pragma unroll
            for (int j = 0; j < 4; j++) {
                int cc = c4 + j;
                int lg = cc & 7;
                int phys = (cc & ~7) + (lg & 3)*2 + (lg >> 2);
                As[r][phys] = f2tf32(vv[j]);
            }
        }
        #pragma unroll
        for (int it = 0; it < 4; it++) {
            int f = tid + it*256;
            int r = f >> 5;
            int n4 = (f & 31)*4;
            float4 v = *(const float4*)&W[(long)(kk + r)*N + col0 + n4];
            float4 o;
            o.x = f2tf32(v.x); o.y = f2tf32(v.y);
            o.z = f2tf32(v.z); o.w = f2tf32(v.w);
            *(float4*)&Ws[r][n4] = o;
        }
        __syncthreads();

        #pragma unroll
        for (int ks = 0; ks < 4; ks++) {
            unsigned a[2][4];
            #pragma unroll
            for (int mt = 0; mt < 2; mt++) {
                int r = wm*32 + mt*16 + (lane >> 2);
                float2 lo = *(const float2*)&As[r][ks*8 + (lane & 3)*2];
                float2 hi = *(const float2*)&As[r + 8][ks*8 + (lane & 3)*2];
                a[mt][0] = __float_as_uint(lo.x);
                a[mt][1] = __float_as_uint(hi.x);
                a[mt][2] = __float_as_uint(lo.y);
                a[mt][3] = __float_as_uint(hi.y);
            }
            unsigned bb[8][2];
            #pragma unroll
            for (int nt = 0; nt < 8; nt++) {
                int n = wn*64 + nt*8 + (lane >> 2);
                bb[nt][0] = __float_as_uint(Ws[ks*8 + (lane & 3)][n]);
                bb[nt][1] = __float_as_uint(Ws[ks*8 + (lane & 3) + 4][n]);
            }
            #pragma unroll
            for (int mt = 0; mt < 2; mt++) {
                #pragma unroll
                for (int nt = 0; nt < 8; nt++) {
                    mma_tf32(c[mt][nt][0], c[mt][nt][1], c[mt][nt][2], c[mt][nt][3],
                             a[mt][0], a[mt][1], a[mt][2], a[mt][3],
                             bb[nt][0], bb[nt][1]);
                }
            }
        }
    }

    #pragma unroll
    for (int mt = 0; mt < 2; mt++) {
        #pragma unroll
        for (int nt = 0; nt < 8; nt++) {
            int row = row0 + wm*32 + mt*16 + (lane >> 2);
            int col = col0 + wn*64 + nt*8 + (lane & 3)*2;
            float2 p0; p0.x = c[mt][nt][0]; p0.y = c[mt][nt][1];
            float2 p1; p1.x = c[mt][nt][2]; p1.y = c[mt][nt][3];
            *(float2*)&C[(long)row*N + col] = p0;
            *(float2*)&C[(long)(row + 8)*N + col] = p1;
        }
    }
}

// ---------------------------------------------------------------------------
// fp16 tensor-core GEMM: C[M,N](fp32) = A[M,K](fp32) @ Wh[K,N](fp16)
// BM=128, BN=64, BK=32, 256 threads = 8 warps (4M x 2N), warp tile 32x32.
// A converted fp32->fp16 during smem staging; ldmatrix fragments.
// ---------------------------------------------------------------------------
__global__ __launch_bounds__(256) void gemm_f16(
    const float* __restrict__ A,
    const __half* __restrict__ Wh,
    const float* __restrict__ bias,
    float* __restrict__ C,
    int M, int K, int N, int relu)
{
    __shared__ __half As[128][40];   // [m][k], pad 40
    __shared__ __half Ws[32][72];    // [k][n], pad 72

    int tid = threadIdx.x;
    int w = tid >> 5, lane = tid & 31;
    int wm = w >> 1, wn = w & 1;     // warp grid 4(M) x 2(N)
    int row0 = blockIdx.y * 128;
    int col0 = blockIdx.x * 64;

    float c[2][4][4];
    #pragma unroll
    for (int mt = 0; mt < 2; mt++)
        #pragma unroll
        for (int nt = 0; nt < 4; nt++)
            #pragma unroll
            for (int r = 0; r < 4; r++)
                c[mt][nt][r] = 0.0f;

    for (int kk = 0; kk < K; kk += 32) {
        __syncthreads();
        // stage A: 128x32 fp32 -> fp16
        #pragma unroll
        for (int it = 0; it < 4; it++) {
            int f = tid + it*256;
            int r = f >> 3, c4 = (f & 7)*4;
            float4 v = *(const float4*)&A[(long)(row0 + r)*K + kk + c4];
            uint2 u;
            u.x = pack_h2(v.x, v.y);
            u.y = pack_h2(v.z, v.w);
            *(uint2*)&As[r][c4] = u;
        }
        // stage W: 32x64 fp16 (1 uint4 per thread)
        {
            int r = tid >> 3, c8 = (tid & 7)*8;
            *(uint4*)&Ws[r][c8] = *(const uint4*)&Wh[(long)(kk + r)*N + col0 + c8];
        }
        __syncthreads();

        #pragma unroll
        for (int kc = 0; kc < 2; kc++) {
            unsigned a[2][4];
            #pragma unroll
            for (int mt = 0; mt < 2; mt++) {
                ldsm_x4(a[mt][0], a[mt][1], a[mt][2], a[mt][3],
                        smem_u32(&As[wm*32 + mt*16 + (lane & 15)][kc*16 + (lane >> 4)*8]));
            }
            unsigned bb[2][4];
            #pragma unroll
            for (int np = 0; np < 2; np++) {
                ldsm_x4_t(bb[np][0], bb[np][1], bb[np][2], bb[np][3],
                          smem_u32(&Ws[kc*16 + (lane & 15)][wn*32 + np*16 + (lane >> 4)*8]));
            }
            #pragma unroll
            for (int mt = 0; mt < 2; mt++) {
                #pragma unroll
                for (int nt = 0; nt < 4; nt++) {
                    unsigned b0 = bb[nt >> 1][(nt & 1)*2 + 0];
                    unsigned b1 = bb[nt >> 1][(nt & 1)*2 + 1];
                    mma_f16(c[mt][nt][0], c[mt][nt][1], c[mt][nt][2], c[mt][nt][3],
                            a[mt][0], a[mt][1], a[mt][2], a[mt][3], b0, b1);
                }
            }
        }
    }

    #pragma unroll
    for (int mt = 0; mt < 2; mt++) {
        #pragma unroll
        for (int nt = 0; nt < 4; nt++) {
            int row = row0 + wm*32 + mt*16 + (lane >> 2);
            int col = col0 + wn*32 + nt*8 + (lane & 3)*2;
            float v0 = c[mt][nt][0];
            float v1 = c[mt][nt][1];
            float v2 = c[mt][nt][2];
            float v3 = c[mt][nt][3];
            if (bias) {
                float b0 = bias[col], b1 = bias[col + 1];
                v0 += b0; v1 += b1; v2 += b0; v3 += b1;
            }
            if (relu) {
                v0 = fmaxf(v0, 0.0f); v1 = fmaxf(v1, 0.0f);
                v2 = fmaxf(v2, 0.0f); v3 = fmaxf(v3, 0.0f);
            }
            float2 p0; p0.x = v0; p0.y = v1;
            float2 p1; p1.x = v2; p1.y = v3;
            *(float2*)&C[(long)row*N + col] = p0;
            *(float2*)&C[(long)(row + 8)*N + col] = p1;
        }
    }
}

// ---------------------------------------------------------------------------
// Rope + split: qkv (TOK,768) -> fp16 Q,K,V in (bh, n, 32) layout.
// ---------------------------------------------------------------------------
__global__ void rope_kernel(const float* __restrict__ qkv,
                            const float* __restrict__ rope,
                            __half* __restrict__ Q,
                            __half* __restrict__ K,
                            __half* __restrict__ V)
{
    int t = blockIdx.x;
    int tid = threadIdx.x;
    int hh = tid >> 5, d = tid & 31;
    int b = t >> 11, n = t & 2047;

    const float* base = qkv + (long)t*768;
    float qv = base[tid];
    float kv = base[256 + tid];
    float vv = base[512 + tid];

    int axis = d >> 4;
    int dd = d & 15;
    int i = dd & 7;
    const float* rp = rope + t*32 + axis*16;
    float c = rp[i], s = rp[8 + i];

    float q2, k2;
    if (dd < 8) {
        float qy = base[tid + 8], ky = base[256 + tid + 8];
        q2 = qv*c - qy*s;
        k2 = kv*c - ky*s;
    } else {
        float qx = base[tid - 8], kx = base[256 + tid - 8];
        q2 = qx*s + qv*c;
        k2 = kx*s + kv*c;
    }

    int bh = b*HH + hh;
    long o = (((long)bh)*NN + n)*DH + d;
    Q[o] = __float2half(q2 * QK_SCALE_LOG2E);
    K[o] = __float2half(k2);
    V[o] = __float2half(vv);
}

// ---------------------------------------------------------------------------
// Flash attention (unchanged from R8 -- verified correct)
// ---------------------------------------------------------------------------
__global__ __launch_bounds__(128) void attn_kernel(
    const __half* __restrict__ Q,
    const __half* __restrict__ K,
    const __half* __restrict__ V,
    float* __restrict__ O)
{
    __shared__ __half Qs[64][40];
    __shared__ __half Ks[64][40];
    __shared__ __half Vs[64][40];

    int bh = blockIdx.y;
    int qb = blockIdx.x;
    int tid = threadIdx.x;
    int w = tid >> 5;
    int lane = tid & 31;

    const __half* qg = Q + ((long)bh*NN + (long)qb*64)*DH;
    const __half* kg = K + (long)bh*NN*DH;
    const __half* vg = V + (long)bh*NN*DH;

    #pragma unroll
    for (int it = 0; it < 2; it++) {
        int i = tid + it*128;
        int r = i >> 2;
        int c = (i & 3)*8;
        *(uint4*)&Qs[r][c] = *(const uint4*)&qg[r*DH + c];
    }
    if (tid < 64) {
        uint4 ones;
        ones.x = 0x00003C00u;
        ones.y = 0u; ones.z = 0u; ones.w = 0u;
        *(uint4*)&Vs[tid][32] = ones;
    }
    __syncthreads();

    unsigned qa0[4], qa1[4];
    ldsm_x4(qa0[0], qa0[1], qa0[2], qa0[3],
            smem_u32(&Qs[w*16 + (lane & 15)][(lane >> 4)*8]));
    ldsm_x4(qa1[0], qa1[1], qa1[2], qa1[3],
            smem_u32(&Qs[w*16 + (lane & 15)][16 + (lane >> 4)*8]));

    float m0 = -1e30f, m1 = -1e30f;
    float oa[5][4];
    #pragma unroll
    for (int dn = 0; dn < 5; dn++) {
        oa[dn][0] = 0.0f; oa[dn][1] = 0.0f; oa[dn][2] = 0.0f; oa[dn][3] = 0.0f;
    }

    for (int kt = 0; kt < NN; kt += 64) {
        __syncthreads();
        #pragma unroll
        for (int it = 0; it < 2; it++) {
            int i = tid + it*128;
            int r = i >> 2;
            int c = (i & 3)*8;
            *(uint4*)&Ks[r][c] = *(const uint4*)&kg[(long)(kt + r)*DH + c];
            *(uint4*)&Vs[r][c] = *(const uint4*)&vg[(long)(kt + r)*DH + c];
        }
        __syncthreads();

        float sc[8][4];
        #pragma unroll
        for (int j = 0; j < 8; j++) {
            sc[j][0] = 0.0f; sc[j][1] = 0.0f; sc[j][2] = 0.0f; sc[j][3] = 0.0f;
        }
        #pragma unroll
        for (int j = 0; j < 8; j++) {
            unsigned b0, b1;
            ldsm_x2(b0, b1, smem_u32(&Ks[j*8 + (lane & 7)][((lane >> 3) & 1)*8]));
            mma_f16(sc[j][0], sc[j][1], sc[j][2], sc[j][3],
                    qa0[0], qa0[1], qa0[2], qa0[3], b0, b1);
            ldsm_x2(b0, b1, smem_u32(&Ks[j*8 + (lane & 7)][16 + ((lane >> 3) & 1)*8]));
            mma_f16(sc[j][0], sc[j][1], sc[j][2], sc[j][3],
                    qa1[0], qa1[1], qa1[2], qa1[3], b0, b1);
        }

        float mx0 = -1e30f, mx1 = -1e30f;
        #pragma unroll
        for (int j = 0; j < 8; j++) {
            mx0 = fmaxf(mx0, fmaxf(sc[j][0], sc[j][1]));
            mx1 = fmaxf(mx1, fmaxf(sc[j][2], sc[j][3]));
        }
        mx0 = fmaxf(mx0, __shfl_xor_sync(0xffffffffu, mx0, 1));
        mx0 = fmaxf(mx0, __shfl_xor_sync(0xffffffffu, mx0, 2));
        mx1 = fmaxf(mx1, __shfl_xor_sync(0xffffffffu, mx1, 1));
        mx1 = fmaxf(mx1, __shfl_xor_sync(0xffffffffu, mx1, 2));
        float mn0 = fmaxf(m0, mx0);
        float mn1 = fmaxf(m1, mx1);
        float corr0 = exp2f(m0 - mn0);
        float corr1 = exp2f(m1 - mn1);
        m0 = mn0; m1 = mn1;
        #pragma unroll
        for (int dn = 0; dn < 5; dn++) {
            oa[dn][0] *= corr0; oa[dn][1] *= corr0;
            oa[dn][2] *= corr1; oa[dn][3] *= corr1;
        }

        unsigned pa[4][4];
        #pragma unroll
        for (int j = 0; j < 8; j++) {
            __half2 e0 = h2exp2(__floats2half2_rn(sc[j][0] - mn0, sc[j][1] - mn0));
            __half2 e1 = h2exp2(__floats2half2_rn(sc[j][2] - mn1, sc[j][3] - mn1));
            pa[j >> 1][(j & 1)*2 + 0] = h2_bits(e0);
            pa[j >> 1][(j & 1)*2 + 1] = h2_bits(e1);
        }

        #pragma unroll
        for (int kc = 0; kc < 4; kc++) {
            #pragma unroll
            for (int dn = 0; dn < 5; dn++) {
                unsigned b0, b1;
                ldsm_x2_t(b0, b1, smem_u32(&Vs[kc*16 + (lane & 15)][dn*8]));
                mma_f16(oa[dn][0], oa[dn][1], oa[dn][2], oa[dn][3],
                        pa[kc][0], pa[kc][1], pa[kc][2], pa[kc][3], b0, b1);
            }
        }
    }

    int src = lane & 28;
    float l0 = __shfl_sync(0xffffffffu, oa[4][0], src);
    float l1 = __shfl_sync(0xffffffffu, oa[4][2], src);

    int b = bh >> 3;
    int hh = bh & 7;
    int q0 = qb*64 + w*16 + (lane >> 2);
    float inv0 = 1.0f / l0;
    float inv1 = 1.0f / l1;
    #pragma unroll
    for (int dn = 0; dn < 4; dn++) {
        int col = hh*DH + dn*8 + (lane & 3)*2;
        float* o0 = &O[((long)b*NN + q0)*DD + col];
        o0[0] = oa[dn][0]*inv0;
        o0[1] = oa[dn][1]*inv0;
        float* o1 = &O[((long)b*NN + q0 + 8)*DD + col];
        o1[0] = oa[dn][2]*inv1;
        o1[1] = oa[dn][3]*inv1;
    }
}

// ---------------------------------------------------------------------------
// h = LayerNorm(h + r) * g + b      (block per token, 256 threads)
// ---------------------------------------------------------------------------
__global__ void add_ln_kernel(float* __restrict__ h,
                              const float* __restrict__ r,
                              const float* __restrict__ g,
                              const float* __restrict__ bta)
{
    int t = blockIdx.x, d = threadIdx.x;
    __shared__ float red[8];

    float x = h[(long)t*DD + d] + r[(long)t*DD + d];

    float s = x;
    #pragma unroll
    for (int o = 16; o > 0; o >>= 1) s += __shfl_xor_sync(0xffffffffu, s, o);
    if ((d & 31) == 0) red[d >> 5] = s;
    __syncthreads();
    float tot = 0.0f;
    #pragma unroll
    for (int i = 0; i < 8; i++) tot += red[i];
    float mean = tot * (1.0f/256.0f);
    float dx = x - mean;
    __syncthreads();

    float s2 = dx*dx;
    #pragma unroll
    for (int o = 16; o > 0; o >>= 1) s2 += __shfl_xor_sync(0xffffffffu, s2, o);
    if ((d & 31) == 0) red[d >> 5] = s2;
    __syncthreads();
    float ssq = 0.0f;
    #pragma unroll
    for (int i = 0; i < 8; i++) ssq += red[i];
    float var = ssq * (1.0f/256.0f);

    h[(long)t*DD + d] = dx * rsqrtf(var + LN_EPS) * g[d] + bta[d];
}

// ---------------------------------------------------------------------------
// Launcher
// ---------------------------------------------------------------------------
extern "C" void kernel_launch(void* const* d_in, const int* in_sizes, int n_in,
                              void* d_out, int out_size)
{
    const float* h_in    = (const float*)d_in[0];
    const float* pos     = (const float*)d_in[1];
    const float* proj_w  = (const float*)d_in[2];
    const float* proj_b  = (const float*)d_in[3];
    const float* qkv_w   = (const float*)d_in[4];
    const float* out_w   = (const float*)d_in[5];
    const float* out_b   = (const float*)d_in[6];
    const float* O_w     = (const float*)d_in[7];
    const float* O_b     = (const float*)d_in[8];
    const float* ffn1_w  = (const float*)d_in[9];
    const float* ffn1_b  = (const float*)d_in[10];
    const float* ffn2_w  = (const float*)d_in[11];
    const float* ffn2_b  = (const float*)d_in[12];
    const float* ln1_g   = (const float*)d_in[13];
    const float* ln1_b   = (const float*)d_in[14];
    const float* ln2_g   = (const float*)d_in[15];
    const float* ln2_b   = (const float*)d_in[16];
    const float* final_w = (const float*)d_in[17];

    float* h;
    float* qkv;
    float* o;
    float* t1;
    float* t2;
    float* rope;
    float* wc;
    float* bc;
    __half* q;
    __half* k;
    __half* v;
    __half* qkvw_h;
    __half* wc_h;
    __half* ffn1w_h;
    __half* ffn2w_h;
    __half* finw_h;
    cudaGetSymbolAddress((void**)&h,    g_h);
    cudaGetSymbolAddress((void**)&qkv,  g_qkv);
    cudaGetSymbolAddress((void**)&q,    g_q);
    cudaGetSymbolAddress((void**)&k,    g_k);
    cudaGetSymbolAddress((void**)&v,    g_v);
    cudaGetSymbolAddress((void**)&o,    g_o);
    cudaGetSymbolAddress((void**)&t1,   g_t1);
    cudaGetSymbolAddress((void**)&t2,   g_t2);
    cudaGetSymbolAddress((void**)&rope, g_rope);
    cudaGetSymbolAddress((void**)&wc,   g_wc);
    cudaGetSymbolAddress((void**)&bc,   g_bc);
    cudaGetSymbolAddress((void**)&qkvw_h,  g_qkvw_h);
    cudaGetSymbolAddress((void**)&wc_h,    g_wc_h);
    cudaGetSymbolAddress((void**)&ffn1w_h, g_ffn1w_h);
    cudaGetSymbolAddress((void**)&ffn2w_h, g_ffn2w_h);
    cudaGetSymbolAddress((void**)&finw_h,  g_finw_h);

    // merged out/O projection in tf32 (one-time; precision matters at weight level)
    gemm_tf32<<<dim3(2, 2, LL), 256>>>(out_w, O_w, wc, DD, DD, DD,
                                       (long)DD*DD, (long)DD*DD, (long)DD*DD);
    bias_combine<<<LL, DD>>>(out_b, O_w, O_b, bc);

    // weight conversion fp32 -> fp16 (one-time)
    {
        int n;
        n = LL*DD*3*DD; to_f16_kernel<<<(n/4 + 255)/256, 256>>>(qkv_w,  qkvw_h,  n);
        n = LL*DD*DD;   to_f16_kernel<<<(n/4 + 255)/256, 256>>>(wc,     wc_h,    n);
        n = LL*DD*2*DD; to_f16_kernel<<<(n/4 + 255)/256, 256>>>(ffn1_w, ffn1w_h, n);
        n = LL*2*DD*DD; to_f16_kernel<<<(n/4 + 255)/256, 256>>>(ffn2_w, ffn2w_h, n);
        n = DD*DD;      to_f16_kernel<<<(n/4 + 255)/256, 256>>>(final_w, finw_h, n);
    }

    proj_rope_init<<<TOK, 256>>>(h_in, pos, proj_w, proj_b, h, rope);

    for (int l = 0; l < LL; l++) {
        gemm_f16<<<dim3(12, 64), 256>>>(h, qkvw_h + (long)l*DD*3*DD, nullptr,
                                        qkv, TOK, DD, 3*DD, 0);
        rope_kernel<<<TOK, 256>>>(qkv, rope, q, k, v);
        attn_kernel<<<dim3(NN/64, BB*HH), 128>>>(q, k, v, o);
        gemm_f16<<<dim3(4, 64), 256>>>(o, wc_h + (long)l*DD*DD, bc + l*DD,
                                       t2, TOK, DD, DD, 0);
        add_ln_kernel<<<TOK, 256>>>(h, t2, ln1_g + l*DD, ln1_b + l*DD);
        gemm_f16<<<dim3(8, 64), 256>>>(h, ffn1w_h + (long)l*DD*2*DD, ffn1_b + l*2*DD,
                                       t1, TOK, DD, 2*DD, 1);
        gemm_f16<<<dim3(4, 64), 256>>>(t1, ffn2w_h + (long)l*2*DD*DD, ffn2_b + l*DD,
                                       o, TOK, 2*DD, DD, 0);
        add_ln_kernel<<<TOK, 256>>>(h, o, ln2_g + l*DD, ln2_b + l*DD);
    }

    gemm_f16<<<dim3(4, 64), 256>>>(h, finw_h, nullptr,
                                   (float*)d_out, TOK, DD, DD, 0);
}

// round 15
// speedup vs baseline: 11.2511x; 1.0748x over previous
#include <cuda_runtime.h>
#include <cuda_bf16.h>
#include <cuda_fp16.h>
#include <cstdint>

// ---------------------------------------------------------------------------
// Problem constants
// ---------------------------------------------------------------------------
#define BB 4
#define NN 2048
#define TOK (BB*NN)        // 8192
#define DD 256
#define HH 8
#define DH 32
#define LL 4
#define QK_SCALE 0.17677669529663687f   // 32^-0.5
#define QK_SCALE_LOG2E 0.25503164244492893f
#define LN_EPS 1e-5f

// ---------------------------------------------------------------------------
// Scratch (no allocation allowed -> __device__ globals)
// ---------------------------------------------------------------------------
__device__ float g_h  [TOK*DD];
__device__ float g_qkv[TOK*3*DD];
__device__ __align__(16) __half g_q[TOK*DD];   // (bh, n, d) fp16 (pre-scaled)
__device__ __align__(16) __half g_k[TOK*DD];   // (bh, n, d) fp16
__device__ __align__(16) __half g_v[TOK*DD];   // (bh, n, d) fp16
__device__ float g_o  [TOK*DD];
__device__ float g_t1 [TOK*2*DD];
__device__ float g_t2 [TOK*DD];
__device__ float g_rope[TOK*32];
__device__ float g_wc [LL*DD*DD];  // merged out_w @ O_w (fp32)
__device__ float g_bc [LL*DD];     // merged out_b @ O_w + O_b

// fp16 weight copies
__device__ __align__(16) __half g_qkvw_h [LL*DD*3*DD];
__device__ __align__(16) __half g_wc_h   [LL*DD*DD];
__device__ __align__(16) __half g_ffn1w_h[LL*DD*2*DD];
__device__ __align__(16) __half g_ffn2w_h[LL*2*DD*DD];
__device__ __align__(16) __half g_finw_h [DD*DD];

// ---------------------------------------------------------------------------
// PTX helpers
// ---------------------------------------------------------------------------
__device__ __forceinline__ unsigned smem_u32(const void* p)
{
    return (unsigned)__cvta_generic_to_shared(p);
}

__device__ __forceinline__ void cp_async16(unsigned dst, const void* src)
{
    asm volatile("cp.async.cg.shared.global [%0], [%1], 16;"
        :: "r"(dst), "l"(src));
}

__device__ __forceinline__ void ldsm_x4(unsigned& r0, unsigned& r1,
                                        unsigned& r2, unsigned& r3, unsigned a)
{
    asm volatile("ldmatrix.sync.aligned.m8n8.x4.shared.b16 {%0,%1,%2,%3}, [%4];"
        : "=r"(r0), "=r"(r1), "=r"(r2), "=r"(r3) : "r"(a));
}

__device__ __forceinline__ void ldsm_x4_t(unsigned& r0, unsigned& r1,
                                          unsigned& r2, unsigned& r3, unsigned a)
{
    asm volatile("ldmatrix.sync.aligned.m8n8.x4.trans.shared.b16 {%0,%1,%2,%3}, [%4];"
        : "=r"(r0), "=r"(r1), "=r"(r2), "=r"(r3) : "r"(a));
}

__device__ __forceinline__ void ldsm_x2(unsigned& r0, unsigned& r1, unsigned a)
{
    asm volatile("ldmatrix.sync.aligned.m8n8.x2.shared.b16 {%0,%1}, [%2];"
        : "=r"(r0), "=r"(r1) : "r"(a));
}

__device__ __forceinline__ void ldsm_x2_t(unsigned& r0, unsigned& r1, unsigned a)
{
    asm volatile("ldmatrix.sync.aligned.m8n8.x2.trans.shared.b16 {%0,%1}, [%2];"
        : "=r"(r0), "=r"(r1) : "r"(a));
}

__device__ __forceinline__ void mma_f16(float& c0, float& c1, float& c2, float& c3,
                                        unsigned a0, unsigned a1, unsigned a2, unsigned a3,
                                        unsigned b0, unsigned b1)
{
    asm volatile("mma.sync.aligned.m16n8k16.row.col.f32.f16.f16.f32 "
        "{%0,%1,%2,%3}, {%4,%5,%6,%7}, {%8,%9}, {%0,%1,%2,%3};"
        : "+f"(c0), "+f"(c1), "+f"(c2), "+f"(c3)
        : "r"(a0), "r"(a1), "r"(a2), "r"(a3), "r"(b0), "r"(b1));
}

__device__ __forceinline__ void mma_tf32(float& c0, float& c1, float& c2, float& c3,
                                         unsigned a0, unsigned a1, unsigned a2, unsigned a3,
                                         unsigned b0, unsigned b1)
{
    asm volatile("mma.sync.aligned.m16n8k8.row.col.f32.tf32.tf32.f32 "
        "{%0,%1,%2,%3}, {%4,%5,%6,%7}, {%8,%9}, {%0,%1,%2,%3};"
        : "+f"(c0), "+f"(c1), "+f"(c2), "+f"(c3)
        : "r"(a0), "r"(a1), "r"(a2), "r"(a3), "r"(b0), "r"(b1));
}

__device__ __forceinline__ float f2tf32(float x)
{
    unsigned r;
    asm("cvt.rna.tf32.f32 %0, %1;" : "=r"(r) : "f"(x));
    return __uint_as_float(r);
}

__device__ __forceinline__ unsigned h2_bits(__half2 h)
{
    unsigned u;
    memcpy(&u, &h, 4);
    return u;
}

__device__ __forceinline__ unsigned pack_h2(float lo, float hi)
{
    __half2 t = __floats2half2_rn(lo, hi);
    unsigned u;
    memcpy(&u, &t, 4);
    return u;
}

// ---------------------------------------------------------------------------
// Weight conversion fp32 -> fp16
// ---------------------------------------------------------------------------
__global__ void to_f16_kernel(const float* __restrict__ in,
                              __half* __restrict__ out, int n)
{
    int i = (blockIdx.x*256 + threadIdx.x)*4;
    if (i < n) {
        float4 v = *(const float4*)&in[i];
        uint2 u;
        u.x = pack_h2(v.x, v.y);
        u.y = pack_h2(v.z, v.w);
        *(uint2*)&out[i] = u;
    }
}

// ---------------------------------------------------------------------------
// Kernel 0: input projection (IN_DIM=1 outer product) + rope table
// ---------------------------------------------------------------------------
__global__ void proj_rope_init(const float* __restrict__ h_in,
                               const float* __restrict__ pos,
                               const float* __restrict__ pw,
                               const float* __restrict__ pb,
                               float* __restrict__ h,
                               float* __restrict__ rope)
{
    int t = blockIdx.x;
    int d = threadIdx.x;
    h[t*DD + d] = h_in[t]*pw[d] + pb[d];
    if (d < 16) {
        int axis = d >> 3, i = d & 7;
        float freq = exp2f(-(float)i * (13.287712379549449f / 8.0f));
        float ang = pos[t*2 + axis] * 64.0f * freq;
        float s, c;
        sincosf(ang, &s, &c);
        rope[t*32 + axis*16 + i]     = c;
        rope[t*32 + axis*16 + 8 + i] = s;
    }
}

// ---------------------------------------------------------------------------
// Merged bias: bc[l] = out_b[l] @ O_w[l] + O_b[l]
// ---------------------------------------------------------------------------
__global__ void bias_combine(const float* __restrict__ out_b,
                             const float* __restrict__ O_w,
                             const float* __restrict__ O_b,
                             float* __restrict__ bc)
{
    int l = blockIdx.x;
    int n = threadIdx.x;
    const float* ob = out_b + l*DD;
    const float* Ow = O_w + (long)l*DD*DD;
    float s = O_b[l*DD + n];
    for (int k2 = 0; k2 < DD; k2++)
        s += ob[k2]*Ow[k2*DD + n];
    bc[l*DD + n] = s;
}

// ---------------------------------------------------------------------------
// tf32 GEMM (kept for the one-time wc = out_w @ O_w precompute)
// ---------------------------------------------------------------------------
__global__ __launch_bounds__(256) void gemm_tf32(
    const float* __restrict__ A,
    const float* __restrict__ W,
    float* __restrict__ C,
    int M, int K, int N,
    long batA, long batW, long batC)
{
    __shared__ float As[128][40];
    __shared__ float Ws[32][136];

    A += blockIdx.z*batA;
    W += blockIdx.z*batW;
    C += blockIdx.z*batC;

    int tid = threadIdx.x;
    int w = tid >> 5, lane = tid & 31;
    int wm = w >> 1, wn = w & 1;
    int row0 = blockIdx.y * 128;
    int col0 = blockIdx.x * 128;

    float c[2][8][4];
    #pragma unroll
    for (int mt = 0; mt < 2; mt++)
        #pragma unroll
        for (int nt = 0; nt < 8; nt++)
            #pragma unroll
            for (int r = 0; r < 4; r++)
                c[mt][nt][r] = 0.0f;

    for (int kk = 0; kk < K; kk += 32) {
        __syncthreads();
        #pragma unroll
        for (int it = 0; it < 4; it++) {
            int f = tid + it*256;
            int r = f >> 3;
            int c4 = (f & 7)*4;
            float4 v = *(const float4*)&A[(long)(row0 + r)*K + kk + c4];
            float vv[4] = {v.x, v.y, v.z, v.w};
            #pragma unroll
            for (int j = 0; j < 4; j++) {
                int cc = c4 + j;
                int lg = cc & 7;
                int phys = (cc & ~7) + (lg & 3)*2 + (lg >> 2);
                As[r][phys] = f2tf32(vv[j]);
            }
        }
        #pragma unroll
        for (int it = 0; it < 4; it++) {
            int f = tid + it*256;
            int r = f >> 5;
            int n4 = (f & 31)*4;
            float4 v = *(const float4*)&W[(long)(kk + r)*N + col0 + n4];
            float4 o;
            o.x = f2tf32(v.x); o.y = f2tf32(v.y);
            o.z = f2tf32(v.z); o.w = f2tf32(v.w);
            *(float4*)&Ws[r][n4] = o;
        }
        __syncthreads();

        #pragma unroll
        for (int ks = 0; ks < 4; ks++) {
            unsigned a[2][4];
            #pragma unroll
            for (int mt = 0; mt < 2; mt++) {
                int r = wm*32 + mt*16 + (lane >> 2);
                float2 lo = *(const float2*)&As[r][ks*8 + (lane & 3)*2];
                float2 hi = *(const float2*)&As[r + 8][ks*8 + (lane & 3)*2];
                a[mt][0] = __float_as_uint(lo.x);
                a[mt][1] = __float_as_uint(hi.x);
                a[mt][2] = __float_as_uint(lo.y);
                a[mt][3] = __float_as_uint(hi.y);
            }
            unsigned bb[8][2];
            #pragma unroll
            for (int nt = 0; nt < 8; nt++) {
                int n = wn*64 + nt*8 + (lane >> 2);
                bb[nt][0] = __float_as_uint(Ws[ks*8 + (lane & 3)][n]);
                bb[nt][1] = __float_as_uint(Ws[ks*8 + (lane & 3) + 4][n]);
            }
            #pragma unroll
            for (int mt = 0; mt < 2; mt++) {
                #pragma unroll
                for (int nt = 0; nt < 8; nt++) {
                    mma_tf32(c[mt][nt][0], c[mt][nt][1], c[mt][nt][2], c[mt][nt][3],
                             a[mt][0], a[mt][1], a[mt][2], a[mt][3],
                             bb[nt][0], bb[nt][1]);
                }
            }
        }
    }

    #pragma unroll
    for (int mt = 0; mt < 2; mt++) {
        #pragma unroll
        for (int nt = 0; nt < 8; nt++) {
            int row = row0 + wm*32 + mt*16 + (lane >> 2);
            int col = col0 + wn*64 + nt*8 + (lane & 3)*2;
            float2 p0; p0.x = c[mt][nt][0]; p0.y = c[mt][nt][1];
            float2 p1; p1.x = c[mt][nt][2]; p1.y = c[mt][nt][3];
            *(float2*)&C[(long)row*N + col] = p0;
            *(float2*)&C[(long)(row + 8)*N + col] = p1;
        }
    }
}

// ---------------------------------------------------------------------------
// fp16 tensor-core GEMM: C[M,N](fp32) = A[M,K](fp32) @ Wh[K,N](fp16)
// BM=128, BN=64, BK=32, 256 threads = 8 warps (4M x 2N), warp tile 32x32.
// ---------------------------------------------------------------------------
__global__ __launch_bounds__(256) void gemm_f16(
    const float* __restrict__ A,
    const __half* __restrict__ Wh,
    const float* __restrict__ bias,
    float* __restrict__ C,
    int M, int K, int N, int relu)
{
    __shared__ __half As[128][40];   // [m][k], pad 40
    __shared__ __half Ws[32][72];    // [k][n], pad 72

    int tid = threadIdx.x;
    int w = tid >> 5, lane = tid & 31;
    int wm = w >> 1, wn = w & 1;
    int row0 = blockIdx.y * 128;
    int col0 = blockIdx.x * 64;

    float c[2][4][4];
    #pragma unroll
    for (int mt = 0; mt < 2; mt++)
        #pragma unroll
        for (int nt = 0; nt < 4; nt++)
            #pragma unroll
            for (int r = 0; r < 4; r++)
                c[mt][nt][r] = 0.0f;

    for (int kk = 0; kk < K; kk += 32) {
        __syncthreads();
        #pragma unroll
        for (int it = 0; it < 4; it++) {
            int f = tid + it*256;
            int r = f >> 3, c4 = (f & 7)*4;
            float4 v = *(const float4*)&A[(long)(row0 + r)*K + kk + c4];
            uint2 u;
            u.x = pack_h2(v.x, v.y);
            u.y = pack_h2(v.z, v.w);
            *(uint2*)&As[r][c4] = u;
        }
        {
            int r = tid >> 3, c8 = (tid & 7)*8;
            *(uint4*)&Ws[r][c8] = *(const uint4*)&Wh[(long)(kk + r)*N + col0 + c8];
        }
        __syncthreads();

        #pragma unroll
        for (int kc = 0; kc < 2; kc++) {
            unsigned a[2][4];
            #pragma unroll
            for (int mt = 0; mt < 2; mt++) {
                ldsm_x4(a[mt][0], a[mt][1], a[mt][2], a[mt][3],
                        smem_u32(&As[wm*32 + mt*16 + (lane & 15)][kc*16 + (lane >> 4)*8]));
            }
            unsigned bb[2][4];
            #pragma unroll
            for (int np = 0; np < 2; np++) {
                ldsm_x4_t(bb[np][0], bb[np][1], bb[np][2], bb[np][3],
                          smem_u32(&Ws[kc*16 + (lane & 15)][wn*32 + np*16 + (lane >> 4)*8]));
            }
            #pragma unroll
            for (int mt = 0; mt < 2; mt++) {
                #pragma unroll
                for (int nt = 0; nt < 4; nt++) {
                    unsigned b0 = bb[nt >> 1][(nt & 1)*2 + 0];
                    unsigned b1 = bb[nt >> 1][(nt & 1)*2 + 1];
                    mma_f16(c[mt][nt][0], c[mt][nt][1], c[mt][nt][2], c[mt][nt][3],
                            a[mt][0], a[mt][1], a[mt][2], a[mt][3], b0, b1);
                }
            }
        }
    }

    #pragma unroll
    for (int mt = 0; mt < 2; mt++) {
        #pragma unroll
        for (int nt = 0; nt < 4; nt++) {
            int row = row0 + wm*32 + mt*16 + (lane >> 2);
            int col = col0 + wn*32 + nt*8 + (lane & 3)*2;
            float v0 = c[mt][nt][0];
            float v1 = c[mt][nt][1];
            float v2 = c[mt][nt][2];
            float v3 = c[mt][nt][3];
            if (bias) {
                float b0 = bias[col], b1 = bias[col + 1];
                v0 += b0; v1 += b1; v2 += b0; v3 += b1;
            }
            if (relu) {
                v0 = fmaxf(v0, 0.0f); v1 = fmaxf(v1, 0.0f);
                v2 = fmaxf(v2, 0.0f); v3 = fmaxf(v3, 0.0f);
            }
            float2 p0; p0.x = v0; p0.y = v1;
            float2 p1; p1.x = v2; p1.y = v3;
            *(float2*)&C[(long)row*N + col] = p0;
            *(float2*)&C[(long)(row + 8)*N + col] = p1;
        }
    }
}

// ---------------------------------------------------------------------------
// Rope + split: qkv (TOK,768) -> fp16 Q,K,V in (bh, n, 32) layout.
// ---------------------------------------------------------------------------
__global__ void rope_kernel(const float* __restrict__ qkv,
                            const float* __restrict__ rope,
                            __half* __restrict__ Q,
                            __half* __restrict__ K,
                            __half* __restrict__ V)
{
    int t = blockIdx.x;
    int tid = threadIdx.x;
    int hh = tid >> 5, d = tid & 31;
    int b = t >> 11, n = t & 2047;

    const float* base = qkv + (long)t*768;
    float qv = base[tid];
    float kv = base[256 + tid];
    float vv = base[512 + tid];

    int axis = d >> 4;
    int dd = d & 15;
    int i = dd & 7;
    const float* rp = rope + t*32 + axis*16;
    float c = rp[i], s = rp[8 + i];

    float q2, k2;
    if (dd < 8) {
        float qy = base[tid + 8], ky = base[256 + tid + 8];
        q2 = qv*c - qy*s;
        k2 = kv*c - ky*s;
    } else {
        float qx = base[tid - 8], kx = base[256 + tid - 8];
        q2 = qx*s + qv*c;
        k2 = kx*s + kv*c;
    }

    int bh = b*HH + hh;
    long o = (((long)bh)*NN + n)*DH + d;
    Q[o] = __float2half(q2 * QK_SCALE_LOG2E);
    K[o] = __float2half(k2);
    V[o] = __float2half(vv);
}

// ---------------------------------------------------------------------------
// Flash attention, fp16 mma, base-2 softmax, ones-column denominator.
// NEW (R10->R11): cp.async double-buffered K/V tiles -- prefetch tile t+1
// while computing tile t so the global->smem latency is hidden.
// ---------------------------------------------------------------------------
__global__ __launch_bounds__(128) void attn_kernel(
    const __half* __restrict__ Q,
    const __half* __restrict__ K,
    const __half* __restrict__ V,
    float* __restrict__ O)
{
    __shared__ __half Qs[64][40];
    __shared__ __half Ks[2][64][40];
    __shared__ __half Vs[2][64][40];   // cols 0..31 data; col 32 = 1.0 (both bufs)

    int bh = blockIdx.y;
    int qb = blockIdx.x;
    int tid = threadIdx.x;
    int w = tid >> 5;
    int lane = tid & 31;

    const __half* qg = Q + ((long)bh*NN + (long)qb*64)*DH;
    const __half* kg = K + (long)bh*NN*DH;
    const __half* vg = V + (long)bh*NN*DH;

    // Q tile + ones columns in both V buffers
    #pragma unroll
    for (int it = 0; it < 2; it++) {
        int i = tid + it*128;
        int r = i >> 2;
        int c = (i & 3)*8;
        *(uint4*)&Qs[r][c] = *(const uint4*)&qg[r*DH + c];
    }
    if (tid < 64) {
        uint4 ones;
        ones.x = 0x00003C00u;   // {1.0h, 0}
        ones.y = 0u; ones.z = 0u; ones.w = 0u;
        *(uint4*)&Vs[0][tid][32] = ones;
        *(uint4*)&Vs[1][tid][32] = ones;
    }

    // prefetch tile 0 into buffer 0
    #pragma unroll
    for (int it = 0; it < 2; it++) {
        int i = tid + it*128;
        int r = i >> 2;
        int c = (i & 3)*8;
        cp_async16(smem_u32(&Ks[0][r][c]), &kg[(long)r*DH + c]);
        cp_async16(smem_u32(&Vs[0][r][c]), &vg[(long)r*DH + c]);
    }
    asm volatile("cp.async.commit_group;");
    __syncthreads();

    unsigned qa0[4], qa1[4];
    ldsm_x4(qa0[0], qa0[1], qa0[2], qa0[3],
            smem_u32(&Qs[w*16 + (lane & 15)][(lane >> 4)*8]));
    ldsm_x4(qa1[0], qa1[1], qa1[2], qa1[3],
            smem_u32(&Qs[w*16 + (lane & 15)][16 + (lane >> 4)*8]));

    float m0 = -1e30f, m1 = -1e30f;
    float oa[5][4];
    #pragma unroll
    for (int dn = 0; dn < 5; dn++) {
        oa[dn][0] = 0.0f; oa[dn][1] = 0.0f; oa[dn][2] = 0.0f; oa[dn][3] = 0.0f;
    }

    for (int t = 0; t < NN/64; t++) {
        int cur = t & 1;
        if (t + 1 < NN/64) {
            // prefetch next tile into the other buffer (consumed 2 iters ago;
            // safe: end-of-compute __syncthreads of iter t-1 has passed)
            int nxt = cur ^ 1;
            long base = (long)(t + 1)*64*DH;
            #pragma unroll
            for (int it = 0; it < 2; it++) {
                int i = tid + it*128;
                int r = i >> 2;
                int c = (i & 3)*8;
                cp_async16(smem_u32(&Ks[nxt][r][c]), &kg[base + (long)r*DH + c]);
                cp_async16(smem_u32(&Vs[nxt][r][c]), &vg[base + (long)r*DH + c]);
            }
            asm volatile("cp.async.commit_group;");
            asm volatile("cp.async.wait_group 1;");
        } else {
            asm volatile("cp.async.wait_group 0;");
        }
        __syncthreads();

        // S = Q @ K^T (log2 domain)
        float sc[8][4];
        #pragma unroll
        for (int j = 0; j < 8; j++) {
            sc[j][0] = 0.0f; sc[j][1] = 0.0f; sc[j][2] = 0.0f; sc[j][3] = 0.0f;
        }
        #pragma unroll
        for (int j = 0; j < 8; j++) {
            unsigned b0, b1;
            ldsm_x2(b0, b1, smem_u32(&Ks[cur][j*8 + (lane & 7)][((lane >> 3) & 1)*8]));
            mma_f16(sc[j][0], sc[j][1], sc[j][2], sc[j][3],
                    qa0[0], qa0[1], qa0[2], qa0[3], b0, b1);
            ldsm_x2(b0, b1, smem_u32(&Ks[cur][j*8 + (lane & 7)][16 + ((lane >> 3) & 1)*8]));
            mma_f16(sc[j][0], sc[j][1], sc[j][2], sc[j][3],
                    qa1[0], qa1[1], qa1[2], qa1[3], b0, b1);
        }

        // online softmax (base 2)
        float mx0 = -1e30f, mx1 = -1e30f;
        #pragma unroll
        for (int j = 0; j < 8; j++) {
            mx0 = fmaxf(mx0, fmaxf(sc[j][0], sc[j][1]));
            mx1 = fmaxf(mx1, fmaxf(sc[j][2], sc[j][3]));
        }
        mx0 = fmaxf(mx0, __shfl_xor_sync(0xffffffffu, mx0, 1));
        mx0 = fmaxf(mx0, __shfl_xor_sync(0xffffffffu, mx0, 2));
        mx1 = fmaxf(mx1, __shfl_xor_sync(0xffffffffu, mx1, 1));
        mx1 = fmaxf(mx1, __shfl_xor_sync(0xffffffffu, mx1, 2));
        float mn0 = fmaxf(m0, mx0);
        float mn1 = fmaxf(m1, mx1);
        float corr0 = exp2f(m0 - mn0);
        float corr1 = exp2f(m1 - mn1);
        m0 = mn0; m1 = mn1;
        #pragma unroll
        for (int dn = 0; dn < 5; dn++) {
            oa[dn][0] *= corr0; oa[dn][1] *= corr0;
            oa[dn][2] *= corr1; oa[dn][3] *= corr1;
        }

        // P = 2^(S - m) -> fp16 a-fragments
        unsigned pa[4][4];
        #pragma unroll
        for (int j = 0; j < 8; j++) {
            __half2 e0 = h2exp2(__floats2half2_rn(sc[j][0] - mn0, sc[j][1] - mn0));
            __half2 e1 = h2exp2(__floats2half2_rn(sc[j][2] - mn1, sc[j][3] - mn1));
            pa[j >> 1][(j & 1)*2 + 0] = h2_bits(e0);
            pa[j >> 1][(j & 1)*2 + 1] = h2_bits(e1);
        }

        // O += P @ [V | ones]
        #pragma unroll
        for (int kc = 0; kc < 4; kc++) {
            #pragma unroll
            for (int dn = 0; dn < 5; dn++) {
                unsigned b0, b1;
                ldsm_x2_t(b0, b1, smem_u32(&Vs[cur][kc*16 + (lane & 15)][dn*8]));
                mma_f16(oa[dn][0], oa[dn][1], oa[dn][2], oa[dn][3],
                        pa[kc][0], pa[kc][1], pa[kc][2], pa[kc][3], b0, b1);
            }
        }
        __syncthreads();
    }

    int src = lane & 28;
    float l0 = __shfl_sync(0xffffffffu, oa[4][0], src);
    float l1 = __shfl_sync(0xffffffffu, oa[4][2], src);

    int b = bh >> 3;
    int hh = bh & 7;
    int q0 = qb*64 + w*16 + (lane >> 2);
    float inv0 = 1.0f / l0;
    float inv1 = 1.0f / l1;
    #pragma unroll
    for (int dn = 0; dn < 4; dn++) {
        int col = hh*DH + dn*8 + (lane & 3)*2;
        float* o0 = &O[((long)b*NN + q0)*DD + col];
        o0[0] = oa[dn][0]*inv0;
        o0[1] = oa[dn][1]*inv0;
        float* o1 = &O[((long)b*NN + q0 + 8)*DD + col];
        o1[0] = oa[dn][2]*inv1;
        o1[1] = oa[dn][3]*inv1;
    }
}

// ---------------------------------------------------------------------------
// h = LayerNorm(h + r) * g + b      (block per token, 256 threads)
// ---------------------------------------------------------------------------
__global__ void add_ln_kernel(float* __restrict__ h,
                              const float* __restrict__ r,
                              const float* __restrict__ g,
                              const float* __restrict__ bta)
{
    int t = blockIdx.x, d = threadIdx.x;
    __shared__ float red[8];

    float x = h[(long)t*DD + d] + r[(long)t*DD + d];

    float s = x;
    #pragma unroll
    for (int o = 16; o > 0; o >>= 1) s += __shfl_xor_sync(0xffffffffu, s, o);
    if ((d & 31) == 0) red[d >> 5] = s;
    __syncthreads();
    float tot = 0.0f;
    #pragma unroll
    for (int i = 0; i < 8; i++) tot += red[i];
    float mean = tot * (1.0f/256.0f);
    float dx = x - mean;
    __syncthreads();

    float s2 = dx*dx;
    #pragma unroll
    for (int o = 16; o > 0; o >>= 1) s2 += __shfl_xor_sync(0xffffffffu, s2, o);
    if ((d & 31) == 0) red[d >> 5] = s2;
    __syncthreads();
    float ssq = 0.0f;
    #pragma unroll
    for (int i = 0; i < 8; i++) ssq += red[i];
    float var = ssq * (1.0f/256.0f);

    h[(long)t*DD + d] = dx * rsqrtf(var + LN_EPS) * g[d] + bta[d];
}

// ---------------------------------------------------------------------------
// Launcher
// ---------------------------------------------------------------------------
extern "C" void kernel_launch(void* const* d_in, const int* in_sizes, int n_in,
                              void* d_out, int out_size)
{
    const float* h_in    = (const float*)d_in[0];
    const float* pos     = (const float*)d_in[1];
    const float* proj_w  = (const float*)d_in[2];
    const float* proj_b  = (const float*)d_in[3];
    const float* qkv_w   = (const float*)d_in[4];
    const float* out_w   = (const float*)d_in[5];
    const float* out_b   = (const float*)d_in[6];
    const float* O_w     = (const float*)d_in[7];
    const float* O_b     = (const float*)d_in[8];
    const float* ffn1_w  = (const float*)d_in[9];
    const float* ffn1_b  = (const float*)d_in[10];
    const float* ffn2_w  = (const float*)d_in[11];
    const float* ffn2_b  = (const float*)d_in[12];
    const float* ln1_g   = (const float*)d_in[13];
    const float* ln1_b   = (const float*)d_in[14];
    const float* ln2_g   = (const float*)d_in[15];
    const float* ln2_b   = (const float*)d_in[16];
    const float* final_w = (const float*)d_in[17];

    float* h;
    float* qkv;
    float* o;
    float* t1;
    float* t2;
    float* rope;
    float* wc;
    float* bc;
    __half* q;
    __half* k;
    __half* v;
    __half* qkvw_h;
    __half* wc_h;
    __half* ffn1w_h;
    __half* ffn2w_h;
    __half* finw_h;
    cudaGetSymbolAddress((void**)&h,    g_h);
    cudaGetSymbolAddress((void**)&qkv,  g_qkv);
    cudaGetSymbolAddress((void**)&q,    g_q);
    cudaGetSymbolAddress((void**)&k,    g_k);
    cudaGetSymbolAddress((void**)&v,    g_v);
    cudaGetSymbolAddress((void**)&o,    g_o);
    cudaGetSymbolAddress((void**)&t1,   g_t1);
    cudaGetSymbolAddress((void**)&t2,   g_t2);
    cudaGetSymbolAddress((void**)&rope, g_rope);
    cudaGetSymbolAddress((void**)&wc,   g_wc);
    cudaGetSymbolAddress((void**)&bc,   g_bc);
    cudaGetSymbolAddress((void**)&qkvw_h,  g_qkvw_h);
    cudaGetSymbolAddress((void**)&wc_h,    g_wc_h);
    cudaGetSymbolAddress((void**)&ffn1w_h, g_ffn1w_h);
    cudaGetSymbolAddress((void**)&ffn2w_h, g_ffn2w_h);
    cudaGetSymbolAddress((void**)&finw_h,  g_finw_h);

    gemm_tf32<<<dim3(2, 2, LL), 256>>>(out_w, O_w, wc, DD, DD, DD,
                                       (long)DD*DD, (long)DD*DD, (long)DD*DD);
    bias_combine<<<LL, DD>>>(out_b, O_w, O_b, bc);

    {
        int n;
        n = LL*DD*3*DD; to_f16_kernel<<<(n/4 + 255)/256, 256>>>(qkv_w,  qkvw_h,  n);
        n = LL*DD*DD;   to_f16_kernel<<<(n/4 + 255)/256, 256>>>(wc,     wc_h,    n);
        n = LL*DD*2*DD; to_f16_kernel<<<(n/4 + 255)/256, 256>>>(ffn1_w, ffn1w_h, n);
        n = LL*2*DD*DD; to_f16_kernel<<<(n/4 + 255)/256, 256>>>(ffn2_w, ffn2w_h, n);
        n = DD*DD;      to_f16_kernel<<<(n/4 + 255)/256, 256>>>(final_w, finw_h, n);
    }

    proj_rope_init<<<TOK, 256>>>(h_in, pos, proj_w, proj_b, h, rope);

    for (int l = 0; l < LL; l++) {
        gemm_f16<<<dim3(12, 64), 256>>>(h, qkvw_h + (long)l*DD*3*DD, nullptr,
                                        qkv, TOK, DD, 3*DD, 0);
        rope_kernel<<<TOK, 256>>>(qkv, rope, q, k, v);
        attn_kernel<<<dim3(NN/64, BB*HH), 128>>>(q, k, v, o);
        gemm_f16<<<dim3(4, 64), 256>>>(o, wc_h + (long)l*DD*DD, bc + l*DD,
                                       t2, TOK, DD, DD, 0);
        add_ln_kernel<<<TOK, 256>>>(h, t2, ln1_g + l*DD, ln1_b + l*DD);
        gemm_f16<<<dim3(8, 64), 256>>>(h, ffn1w_h + (long)l*DD*2*DD, ffn1_b + l*2*DD,
                                       t1, TOK, DD, 2*DD, 1);
        gemm_f16<<<dim3(4, 64), 256>>>(t1, ffn2w_h + (long)l*2*DD*DD, ffn2_b + l*DD,
                                       o, TOK, 2*DD, DD, 0);
        add_ln_kernel<<<TOK, 256>>>(h, o, ln2_g + l*DD, ln2_b + l*DD);
    }

    gemm_f16<<<dim3(4, 64), 256>>>(h, finw_h, nullptr,
                                   (float*)d_out, TOK, DD, DD, 0);
}